// round 5
// baseline (speedup 1.0000x reference)
#include <cuda_runtime.h>
#include <cstddef>

// Problem dims (fixed by dataset)
#define NTC 400000
#define NMC 40000
#define CH  64
#define FT  384

// ---------------- scratch (static __device__ — no allocations) ----------------
__device__ float g_xt0[(size_t)NTC * CH];
__device__ float g_xt1[(size_t)NTC * CH];
__device__ float g_xt2[(size_t)NTC * CH];
__device__ float g_aggt[(size_t)NTC * CH];   // scattered pre-transformed mentor rows
__device__ float g_xm0[(size_t)NMC * CH];
__device__ float g_xm1[(size_t)NMC * CH];
__device__ float g_xm2[(size_t)NMC * CH];
__device__ float g_aggm[(size_t)NMC * CH];
__device__ float g_ym[(size_t)NMC * CH];     // y_m = x_m @ Wl_mt^T
__device__ int   g_cnt_t[NTC];
__device__ int   g_cnt_m[NMC];
__device__ float g_inv_t[NTC];
__device__ float g_inv_m[NMC];

// ---------------- packed f32x2 FMA (FFMA2 — only reachable via PTX) ------------
union F2U { float2 f; unsigned long long u; };
__device__ __forceinline__ float2 ffma2(float2 a, float2 b, float2 c) {
    F2U A, B, Cc, D;
    A.f = a; B.f = b; Cc.f = c;
    asm("fma.rn.f32x2 %0, %1, %2, %3;" : "=l"(D.u) : "l"(A.u), "l"(B.u), "l"(Cc.u));
    return D.f;
}

// ---------------- degree / recip ----------------
__global__ void degree_kernel(const int* __restrict__ esrc, const int* __restrict__ edst, int E) {
    int t = blockIdx.x * blockDim.x + threadIdx.x;
    if (t < E) {
        atomicAdd(&g_cnt_t[esrc[t]], 1);
        atomicAdd(&g_cnt_m[edst[t]], 1);
    }
}

__global__ void recip_kernel(const int* __restrict__ cnt, float* __restrict__ inv, int n) {
    int t = blockIdx.x * blockDim.x + threadIdx.x;
    if (t < n) inv[t] = 1.0f / fmaxf((float)cnt[t], 1.0f);
}

// ---------------- mentor encoder: x_m0 = emb_m[mentor_id] ----------------
__global__ void gather_rows_kernel(const float* __restrict__ src, const int* __restrict__ ids,
                                   float* __restrict__ out, int n) {
    int t = blockIdx.x * blockDim.x + threadIdx.x;
    int e = t >> 4;
    if (e >= n) return;
    int c4 = (t & 15) << 2;
    int id = __ldg(&ids[e]);
    float4 v = *reinterpret_cast<const float4*>(&src[(size_t)id * CH + c4]);
    *reinterpret_cast<float4*>(&out[(size_t)e * CH + c4]) = v;
}

// ---------------- edge scatter-add: agg[sidx[e]] += feat[gidx[e]] --------------
__global__ void scatter_kernel(const float* __restrict__ feat, const int* __restrict__ gidx,
                               const int* __restrict__ sidx, float* __restrict__ agg, int E) {
    int t = blockIdx.x * blockDim.x + threadIdx.x;
    int e = t >> 4;
    if (e >= E) return;
    int c4 = (t & 15) << 2;
    int s = __ldg(&gidx[e]);
    int d = __ldg(&sidx[e]);
    float4 v = *reinterpret_cast<const float4*>(&feat[(size_t)s * CH + c4]);
    float* p = &agg[(size_t)d * CH + c4];
    asm volatile("red.global.add.v4.f32 [%0], {%1, %2, %3, %4};"
                 :: "l"(p), "f"(v.x), "f"(v.y), "f"(v.z), "f"(v.w) : "memory");
}

// ============================================================================
// Double-buffered FFMA2 GEMM core: BM=128, BN=64, BK=16, 256 threads.
// Shared W tile stored DUPLICATED (each weight twice, adjacent) so the f32x2
// multiplier is a straight LDS.128 — no packing MOVs in the inner loop.
// Layout per thread: tx = tid&15 -> cols [4tx..4tx+3], ty = tid>>4 ->
// rows [8ty..8ty+7] as 4 row-pairs in f32x2 accumulators.
// ============================================================================
#define BKQ 16

// encoder: out = X[M,384] @ W[64,384]^T + b + emb[ids[row]]
__global__ __launch_bounds__(256)
void encoder_kernel(const float* __restrict__ X, const float* __restrict__ W,
                    const float* __restrict__ bias, const float* __restrict__ emb,
                    const int* __restrict__ ids, float* __restrict__ out, int M) {
    __shared__ float As[2][BKQ][132];
    __shared__ float Wd[2][BKQ][132];
    int tid = threadIdx.x;
    int tx = tid & 15, ty = tid >> 4;
    int row0 = blockIdx.x * 128;

    float2 acc[4][4];
#pragma unroll
    for (int i = 0; i < 4; i++)
#pragma unroll
        for (int j = 0; j < 4; j++) acc[i][j] = make_float2(0.f, 0.f);

    // per-tile gmem->reg prefetch: As 2 float4, W 1 float4 per thread
    float4 ar[2], wr;
    int a_r0 = tid >> 2;               // 0..63  (rows tid>>2 and +64)
    int a_kq = (tid & 3) << 2;         // 0,4,8,12
    int w_c  = tid >> 2;               // 0..63
    // NOTE: same kq for W

    const int NK = FT / BKQ;           // 24

    // ---- prologue: tile 0 ----
    {
        int g0 = row0 + a_r0, g1 = row0 + a_r0 + 64;
        ar[0] = (g0 < M) ? *reinterpret_cast<const float4*>(&X[(size_t)g0 * FT + a_kq])
                         : make_float4(0.f, 0.f, 0.f, 0.f);
        ar[1] = (g1 < M) ? *reinterpret_cast<const float4*>(&X[(size_t)g1 * FT + a_kq])
                         : make_float4(0.f, 0.f, 0.f, 0.f);
        wr = *reinterpret_cast<const float4*>(&W[(size_t)w_c * FT + a_kq]);
        As[0][a_kq + 0][a_r0] = ar[0].x; As[0][a_kq + 1][a_r0] = ar[0].y;
        As[0][a_kq + 2][a_r0] = ar[0].z; As[0][a_kq + 3][a_r0] = ar[0].w;
        As[0][a_kq + 0][a_r0 + 64] = ar[1].x; As[0][a_kq + 1][a_r0 + 64] = ar[1].y;
        As[0][a_kq + 2][a_r0 + 64] = ar[1].z; As[0][a_kq + 3][a_r0 + 64] = ar[1].w;
        Wd[0][a_kq + 0][2 * w_c] = wr.x; Wd[0][a_kq + 0][2 * w_c + 1] = wr.x;
        Wd[0][a_kq + 1][2 * w_c] = wr.y; Wd[0][a_kq + 1][2 * w_c + 1] = wr.y;
        Wd[0][a_kq + 2][2 * w_c] = wr.z; Wd[0][a_kq + 2][2 * w_c + 1] = wr.z;
        Wd[0][a_kq + 3][2 * w_c] = wr.w; Wd[0][a_kq + 3][2 * w_c + 1] = wr.w;
    }
    __syncthreads();

#pragma unroll 2
    for (int it = 0; it < NK; it++) {
        int buf = it & 1;
        bool more = (it + 1 < NK);
        if (more) {
            int kt = (it + 1) * BKQ;
            int g0 = row0 + a_r0, g1 = row0 + a_r0 + 64;
            ar[0] = (g0 < M) ? *reinterpret_cast<const float4*>(&X[(size_t)g0 * FT + kt + a_kq])
                             : make_float4(0.f, 0.f, 0.f, 0.f);
            ar[1] = (g1 < M) ? *reinterpret_cast<const float4*>(&X[(size_t)g1 * FT + kt + a_kq])
                             : make_float4(0.f, 0.f, 0.f, 0.f);
            wr = *reinterpret_cast<const float4*>(&W[(size_t)w_c * FT + kt + a_kq]);
        }
#pragma unroll
        for (int k = 0; k < BKQ; k++) {
            float4 a0 = *reinterpret_cast<const float4*>(&As[buf][k][ty * 8]);
            float4 a1 = *reinterpret_cast<const float4*>(&As[buf][k][ty * 8 + 4]);
            float4 w0 = *reinterpret_cast<const float4*>(&Wd[buf][k][tx * 8]);
            float4 w1 = *reinterpret_cast<const float4*>(&Wd[buf][k][tx * 8 + 4]);
            float2 ap[4] = { {a0.x, a0.y}, {a0.z, a0.w}, {a1.x, a1.y}, {a1.z, a1.w} };
            float2 wd4[4] = { {w0.x, w0.y}, {w0.z, w0.w}, {w1.x, w1.y}, {w1.z, w1.w} };
#pragma unroll
            for (int rp = 0; rp < 4; rp++)
#pragma unroll
                for (int j = 0; j < 4; j++)
                    acc[rp][j] = ffma2(ap[rp], wd4[j], acc[rp][j]);
        }
        if (more) {
            int nb = buf ^ 1;
            As[nb][a_kq + 0][a_r0] = ar[0].x; As[nb][a_kq + 1][a_r0] = ar[0].y;
            As[nb][a_kq + 2][a_r0] = ar[0].z; As[nb][a_kq + 3][a_r0] = ar[0].w;
            As[nb][a_kq + 0][a_r0 + 64] = ar[1].x; As[nb][a_kq + 1][a_r0 + 64] = ar[1].y;
            As[nb][a_kq + 2][a_r0 + 64] = ar[1].z; As[nb][a_kq + 3][a_r0 + 64] = ar[1].w;
            Wd[nb][a_kq + 0][2 * w_c] = wr.x; Wd[nb][a_kq + 0][2 * w_c + 1] = wr.x;
            Wd[nb][a_kq + 1][2 * w_c] = wr.y; Wd[nb][a_kq + 1][2 * w_c + 1] = wr.y;
            Wd[nb][a_kq + 2][2 * w_c] = wr.z; Wd[nb][a_kq + 2][2 * w_c + 1] = wr.z;
            Wd[nb][a_kq + 3][2 * w_c] = wr.w; Wd[nb][a_kq + 3][2 * w_c + 1] = wr.w;
        }
        __syncthreads();
    }

    float4 bv = *reinterpret_cast<const float4*>(&bias[tx * 4]);
#pragma unroll
    for (int rp = 0; rp < 4; rp++) {
#pragma unroll
        for (int s = 0; s < 2; s++) {
            int r = row0 + ty * 8 + rp * 2 + s;
            if (r < M) {
                int nid = __ldg(&ids[r]);
                float4 ev = *reinterpret_cast<const float4*>(&emb[(size_t)nid * CH + tx * 4]);
                float4 o;
                o.x = (s ? acc[rp][0].y : acc[rp][0].x) + bv.x + ev.x;
                o.y = (s ? acc[rp][1].y : acc[rp][1].x) + bv.y + ev.y;
                o.z = (s ? acc[rp][2].y : acc[rp][2].x) + bv.z + ev.z;
                o.w = (s ? acc[rp][3].y : acc[rp][3].x) + bv.w + ev.w;
                *reinterpret_cast<float4*>(&out[(size_t)r * CH + tx * 4]) = o;
            }
        }
    }
}

// K=64 GEMM, same core: out = act( X@W^T [+ bias] [+ aggY*inv] )
template <bool RELU, bool BIAS, bool ADDAGG>
__global__ __launch_bounds__(256)
void gemm64_kernel(const float* __restrict__ X, const float* __restrict__ W,
                   const float* __restrict__ bias,
                   const float* __restrict__ aggY, const float* __restrict__ inv,
                   float* __restrict__ out, int M) {
    __shared__ float As[2][BKQ][132];
    __shared__ float Wd[2][BKQ][132];
    int tid = threadIdx.x;
    int tx = tid & 15, ty = tid >> 4;
    int row0 = blockIdx.x * 128;

    float2 acc[4][4];
#pragma unroll
    for (int i = 0; i < 4; i++)
#pragma unroll
        for (int j = 0; j < 4; j++) acc[i][j] = make_float2(0.f, 0.f);

    float4 ar[2], wr;
    int a_r0 = tid >> 2;
    int a_kq = (tid & 3) << 2;
    int w_c  = tid >> 2;

    const int NK = CH / BKQ;  // 4

    {
        int g0 = row0 + a_r0, g1 = row0 + a_r0 + 64;
        ar[0] = (g0 < M) ? *reinterpret_cast<const float4*>(&X[(size_t)g0 * CH + a_kq])
                         : make_float4(0.f, 0.f, 0.f, 0.f);
        ar[1] = (g1 < M) ? *reinterpret_cast<const float4*>(&X[(size_t)g1 * CH + a_kq])
                         : make_float4(0.f, 0.f, 0.f, 0.f);
        wr = *reinterpret_cast<const float4*>(&W[(size_t)w_c * CH + a_kq]);
        As[0][a_kq + 0][a_r0] = ar[0].x; As[0][a_kq + 1][a_r0] = ar[0].y;
        As[0][a_kq + 2][a_r0] = ar[0].z; As[0][a_kq + 3][a_r0] = ar[0].w;
        As[0][a_kq + 0][a_r0 + 64] = ar[1].x; As[0][a_kq + 1][a_r0 + 64] = ar[1].y;
        As[0][a_kq + 2][a_r0 + 64] = ar[1].z; As[0][a_kq + 3][a_r0 + 64] = ar[1].w;
        Wd[0][a_kq + 0][2 * w_c] = wr.x; Wd[0][a_kq + 0][2 * w_c + 1] = wr.x;
        Wd[0][a_kq + 1][2 * w_c] = wr.y; Wd[0][a_kq + 1][2 * w_c + 1] = wr.y;
        Wd[0][a_kq + 2][2 * w_c] = wr.z; Wd[0][a_kq + 2][2 * w_c + 1] = wr.z;
        Wd[0][a_kq + 3][2 * w_c] = wr.w; Wd[0][a_kq + 3][2 * w_c + 1] = wr.w;
    }
    __syncthreads();

#pragma unroll
    for (int it = 0; it < NK; it++) {
        int buf = it & 1;
        bool more = (it + 1 < NK);
        if (more) {
            int kt = (it + 1) * BKQ;
            int g0 = row0 + a_r0, g1 = row0 + a_r0 + 64;
            ar[0] = (g0 < M) ? *reinterpret_cast<const float4*>(&X[(size_t)g0 * CH + kt + a_kq])
                             : make_float4(0.f, 0.f, 0.f, 0.f);
            ar[1] = (g1 < M) ? *reinterpret_cast<const float4*>(&X[(size_t)g1 * CH + kt + a_kq])
                             : make_float4(0.f, 0.f, 0.f, 0.f);
            wr = *reinterpret_cast<const float4*>(&W[(size_t)w_c * CH + kt + a_kq]);
        }
#pragma unroll
        for (int k = 0; k < BKQ; k++) {
            float4 a0 = *reinterpret_cast<const float4*>(&As[buf][k][ty * 8]);
            float4 a1 = *reinterpret_cast<const float4*>(&As[buf][k][ty * 8 + 4]);
            float4 w0 = *reinterpret_cast<const float4*>(&Wd[buf][k][tx * 8]);
            float4 w1 = *reinterpret_cast<const float4*>(&Wd[buf][k][tx * 8 + 4]);
            float2 ap[4] = { {a0.x, a0.y}, {a0.z, a0.w}, {a1.x, a1.y}, {a1.z, a1.w} };
            float2 wd4[4] = { {w0.x, w0.y}, {w0.z, w0.w}, {w1.x, w1.y}, {w1.z, w1.w} };
#pragma unroll
            for (int rp = 0; rp < 4; rp++)
#pragma unroll
                for (int j = 0; j < 4; j++)
                    acc[rp][j] = ffma2(ap[rp], wd4[j], acc[rp][j]);
        }
        if (more) {
            int nb = buf ^ 1;
            As[nb][a_kq + 0][a_r0] = ar[0].x; As[nb][a_kq + 1][a_r0] = ar[0].y;
            As[nb][a_kq + 2][a_r0] = ar[0].z; As[nb][a_kq + 3][a_r0] = ar[0].w;
            As[nb][a_kq + 0][a_r0 + 64] = ar[1].x; As[nb][a_kq + 1][a_r0 + 64] = ar[1].y;
            As[nb][a_kq + 2][a_r0 + 64] = ar[1].z; As[nb][a_kq + 3][a_r0 + 64] = ar[1].w;
            Wd[nb][a_kq + 0][2 * w_c] = wr.x; Wd[nb][a_kq + 0][2 * w_c + 1] = wr.x;
            Wd[nb][a_kq + 1][2 * w_c] = wr.y; Wd[nb][a_kq + 1][2 * w_c + 1] = wr.y;
            Wd[nb][a_kq + 2][2 * w_c] = wr.z; Wd[nb][a_kq + 2][2 * w_c + 1] = wr.z;
            Wd[nb][a_kq + 3][2 * w_c] = wr.w; Wd[nb][a_kq + 3][2 * w_c + 1] = wr.w;
        }
        __syncthreads();
    }

    float4 bv = make_float4(0.f, 0.f, 0.f, 0.f);
    if (BIAS) bv = *reinterpret_cast<const float4*>(&bias[tx * 4]);
#pragma unroll
    for (int rp = 0; rp < 4; rp++) {
#pragma unroll
        for (int s = 0; s < 2; s++) {
            int r = row0 + ty * 8 + rp * 2 + s;
            if (r < M) {
                float4 o;
                o.x = (s ? acc[rp][0].y : acc[rp][0].x) + bv.x;
                o.y = (s ? acc[rp][1].y : acc[rp][1].x) + bv.y;
                o.z = (s ? acc[rp][2].y : acc[rp][2].x) + bv.z;
                o.w = (s ? acc[rp][3].y : acc[rp][3].x) + bv.w;
                if (ADDAGG) {
                    float sc = __ldg(&inv[r]);
                    float4 av = *reinterpret_cast<const float4*>(&aggY[(size_t)r * CH + tx * 4]);
                    o.x = fmaf(av.x, sc, o.x);
                    o.y = fmaf(av.y, sc, o.y);
                    o.z = fmaf(av.z, sc, o.z);
                    o.w = fmaf(av.w, sc, o.w);
                }
                if (RELU) {
                    o.x = fmaxf(o.x, 0.f); o.y = fmaxf(o.y, 0.f);
                    o.z = fmaxf(o.z, 0.f); o.w = fmaxf(o.w, 0.f);
                }
                *reinterpret_cast<float4*>(&out[(size_t)r * CH + tx * 4]) = o;
            }
        }
    }
}

// ---------------- mentor SAGE layer GEMM (K=128: agg/inv + self) ---------------
template <bool RELU>
__global__ __launch_bounds__(256)
void sage_kernel(const float* __restrict__ Agg, const float* __restrict__ inv,
                 const float* __restrict__ Xs,
                 const float* __restrict__ Wl, const float* __restrict__ Wr,
                 const float* __restrict__ bias, float* __restrict__ out, int M) {
    __shared__ float As[32][132];
    __shared__ float Ws[32][68];
    int tid = threadIdx.x;
    int tx = tid & 15, ty = tid >> 4;
    int row0 = blockIdx.x * 128;

    float2 acc[4][4];
#pragma unroll
    for (int i = 0; i < 4; i++)
#pragma unroll
        for (int j = 0; j < 4; j++) acc[i][j] = make_float2(0.f, 0.f);

    for (int tt = 0; tt < 4; tt++) {
        const float* A  = (tt < 2) ? Agg : Xs;
        const float* Wp = (tt < 2) ? Wl  : Wr;
        bool do_scale = (tt < 2);
        int kt = (tt & 1) * 32;
#pragma unroll
        for (int i = 0; i < 4; i++) {
            int idx = tid + 256 * i;
            int r = idx >> 3;
            int kq = (idx & 7) << 2;
            int grow = row0 + r;
            float4 v = make_float4(0.f, 0.f, 0.f, 0.f);
            if (grow < M) {
                v = *reinterpret_cast<const float4*>(&A[(size_t)grow * CH + kt + kq]);
                if (do_scale) {
                    float sc = __ldg(&inv[grow]);
                    v.x *= sc; v.y *= sc; v.z *= sc; v.w *= sc;
                }
            }
            As[kq + 0][r] = v.x; As[kq + 1][r] = v.y;
            As[kq + 2][r] = v.z; As[kq + 3][r] = v.w;
        }
#pragma unroll
        for (int i = 0; i < 2; i++) {
            int idx = tid + 256 * i;
            int c = idx >> 3;
            int kq = (idx & 7) << 2;
            float4 v = *reinterpret_cast<const float4*>(&Wp[(size_t)c * CH + kt + kq]);
            Ws[kq + 0][c] = v.x; Ws[kq + 1][c] = v.y;
            Ws[kq + 2][c] = v.z; Ws[kq + 3][c] = v.w;
        }
        __syncthreads();
#pragma unroll
        for (int k = 0; k < 32; k++) {
            float4 a0 = *reinterpret_cast<const float4*>(&As[k][ty * 8]);
            float4 a1 = *reinterpret_cast<const float4*>(&As[k][ty * 8 + 4]);
            float4 w  = *reinterpret_cast<const float4*>(&Ws[k][tx * 4]);
            float2 ap[4] = { {a0.x, a0.y}, {a0.z, a0.w}, {a1.x, a1.y}, {a1.z, a1.w} };
            float2 wd[4] = { {w.x, w.x}, {w.y, w.y}, {w.z, w.z}, {w.w, w.w} };
#pragma unroll
            for (int rp = 0; rp < 4; rp++)
#pragma unroll
                for (int j = 0; j < 4; j++)
                    acc[rp][j] = ffma2(ap[rp], wd[j], acc[rp][j]);
        }
        __syncthreads();
    }

    float4 bv = *reinterpret_cast<const float4*>(&bias[tx * 4]);
#pragma unroll
    for (int rp = 0; rp < 4; rp++) {
#pragma unroll
        for (int s = 0; s < 2; s++) {
            int r = row0 + ty * 8 + rp * 2 + s;
            if (r < M) {
                float4 o;
                o.x = (s ? acc[rp][0].y : acc[rp][0].x) + bv.x;
                o.y = (s ? acc[rp][1].y : acc[rp][1].x) + bv.y;
                o.z = (s ? acc[rp][2].y : acc[rp][2].x) + bv.z;
                o.w = (s ? acc[rp][3].y : acc[rp][3].x) + bv.w;
                if (RELU) {
                    o.x = fmaxf(o.x, 0.f); o.y = fmaxf(o.y, 0.f);
                    o.z = fmaxf(o.z, 0.f); o.w = fmaxf(o.w, 0.f);
                }
                *reinterpret_cast<float4*>(&out[(size_t)r * CH + tx * 4]) = o;
            }
        }
    }
}

// ---------------- edge dot-product classifier --------------------------------
__global__ void edge_dot_kernel(const float* __restrict__ xt, const float* __restrict__ xm,
                                const int* __restrict__ es, const int* __restrict__ ed,
                                float* __restrict__ out, int E) {
    int t = blockIdx.x * blockDim.x + threadIdx.x;
    int e = t >> 4;
    if (e >= E) return;
    int c4 = (t & 15) << 2;
    int s = __ldg(&es[e]);
    int d = __ldg(&ed[e]);
    float4 a = *reinterpret_cast<const float4*>(&xt[(size_t)s * CH + c4]);
    float4 b = *reinterpret_cast<const float4*>(&xm[(size_t)d * CH + c4]);
    float p = a.x * b.x + a.y * b.y + a.z * b.z + a.w * b.w;
    p += __shfl_down_sync(0xffffffffu, p, 8);
    p += __shfl_down_sync(0xffffffffu, p, 4);
    p += __shfl_down_sync(0xffffffffu, p, 2);
    p += __shfl_down_sync(0xffffffffu, p, 1);
    if ((t & 15) == 0) out[e] = p;
}

// ---------------- launch -----------------------------------------------------
extern "C" void kernel_launch(void* const* d_in, const int* in_sizes, int n_in,
                              void* d_out, int out_size) {
    const float* x_thesis  = (const float*)d_in[0];
    const int*   thesis_id = (const int*)d_in[1];
    const int*   mentor_id = (const int*)d_in[2];
    const int*   edge_src  = (const int*)d_in[3];
    const int*   edge_dst  = (const int*)d_in[4];
    const int*   el_src    = (const int*)d_in[5];
    const int*   el_dst    = (const int*)d_in[6];
    const float* lin_W     = (const float*)d_in[7];
    const float* lin_b     = (const float*)d_in[8];
    const float* emb_t     = (const float*)d_in[9];
    const float* emb_m     = (const float*)d_in[10];
    const float* Wl_tm0    = (const float*)d_in[11];
    const float* Wr_tm0    = (const float*)d_in[12];
    const float* b_tm0     = (const float*)d_in[13];
    const float* Wl_mt0    = (const float*)d_in[14];
    const float* Wr_mt0    = (const float*)d_in[15];
    const float* b_mt0     = (const float*)d_in[16];
    const float* Wl_tm1    = (const float*)d_in[17];
    const float* Wr_tm1    = (const float*)d_in[18];
    const float* b_tm1     = (const float*)d_in[19];
    const float* Wl_mt1    = (const float*)d_in[20];
    const float* Wr_mt1    = (const float*)d_in[21];
    const float* b_mt1     = (const float*)d_in[22];
    float* out = (float*)d_out;

    int nt = in_sizes[1];
    int nm = in_sizes[2];
    int E  = in_sizes[3];
    int EL = in_sizes[5];

    void *p_xt0, *p_xt1, *p_xt2, *p_aggt, *p_xm0, *p_xm1, *p_xm2, *p_aggm, *p_ym;
    void *p_cntt, *p_cntm, *p_invt, *p_invm;
    cudaGetSymbolAddress(&p_xt0, g_xt0);   cudaGetSymbolAddress(&p_xt1, g_xt1);
    cudaGetSymbolAddress(&p_xt2, g_xt2);   cudaGetSymbolAddress(&p_aggt, g_aggt);
    cudaGetSymbolAddress(&p_xm0, g_xm0);   cudaGetSymbolAddress(&p_xm1, g_xm1);
    cudaGetSymbolAddress(&p_xm2, g_xm2);   cudaGetSymbolAddress(&p_aggm, g_aggm);
    cudaGetSymbolAddress(&p_ym, g_ym);
    cudaGetSymbolAddress(&p_cntt, g_cnt_t); cudaGetSymbolAddress(&p_cntm, g_cnt_m);
    cudaGetSymbolAddress(&p_invt, g_inv_t); cudaGetSymbolAddress(&p_invm, g_inv_m);

    float* xt0 = (float*)p_xt0; float* xt1 = (float*)p_xt1; float* xt2 = (float*)p_xt2;
    float* aggt = (float*)p_aggt;
    float* xm0 = (float*)p_xm0; float* xm1 = (float*)p_xm1; float* xm2 = (float*)p_xm2;
    float* aggm = (float*)p_aggm; float* ym = (float*)p_ym;
    int* cntt = (int*)p_cntt; int* cntm = (int*)p_cntm;
    float* invt = (float*)p_invt; float* invm = (float*)p_invm;

    const int TB = 256;
    int gridE16  = (E * 16 + TB - 1) / TB;
    int gridEL16 = (EL * 16 + TB - 1) / TB;
    int gridNT   = (nt + 127) / 128;
    int gridNM   = (nm + 127) / 128;

    // ---- phase A: exactly 5 launches before the encoder so ncu (-s 5 -c 1)
    //      keeps capturing encoder_kernel ----
    cudaMemsetAsync(cntt, 0, (size_t)nt * sizeof(int));
    cudaMemsetAsync(cntm, 0, (size_t)nm * sizeof(int));
    degree_kernel<<<(E + TB - 1) / TB, TB>>>(edge_src, edge_dst, E);
    recip_kernel<<<(nt + TB - 1) / TB, TB>>>(cntt, invt, nt);
    recip_kernel<<<(nm + TB - 1) / TB, TB>>>(cntm, invm, nm);

    encoder_kernel<<<gridNT, TB>>>(x_thesis, lin_W, lin_b, emb_t, thesis_id, xt0, nt);
    gather_rows_kernel<<<(nm * 16 + TB - 1) / TB, TB>>>(emb_m, mentor_id, xm0, nm);

    // ---- layer 0 ----
    // pre-transform mentor rows for thesis aggregation: y_m = x_m @ Wl_mt0^T
    gemm64_kernel<false, false, false><<<gridNM, TB>>>(xm0, Wl_mt0, nullptr, nullptr, nullptr, ym, nm);
    cudaMemsetAsync(aggm, 0, (size_t)nm * CH * sizeof(float));
    cudaMemsetAsync(aggt, 0, (size_t)nt * CH * sizeof(float));
    scatter_kernel<<<gridE16, TB>>>(xt0, edge_src, edge_dst, aggm, E);
    scatter_kernel<<<gridE16, TB>>>(ym, edge_dst, edge_src, aggt, E);
    sage_kernel<true><<<gridNM, TB>>>(aggm, invm, xm0, Wl_tm0, Wr_tm0, b_tm0, xm1, nm);
    gemm64_kernel<true, true, true><<<gridNT, TB>>>(xt0, Wr_mt0, b_mt0, aggt, invt, xt1, nt);

    // ---- layer 1 ----
    gemm64_kernel<false, false, false><<<gridNM, TB>>>(xm1, Wl_mt1, nullptr, nullptr, nullptr, ym, nm);
    cudaMemsetAsync(aggm, 0, (size_t)nm * CH * sizeof(float));
    cudaMemsetAsync(aggt, 0, (size_t)nt * CH * sizeof(float));
    scatter_kernel<<<gridE16, TB>>>(xt1, edge_src, edge_dst, aggm, E);
    scatter_kernel<<<gridE16, TB>>>(ym, edge_dst, edge_src, aggt, E);
    sage_kernel<false><<<gridNM, TB>>>(aggm, invm, xm1, Wl_tm1, Wr_tm1, b_tm1, xm2, nm);
    gemm64_kernel<false, true, true><<<gridNT, TB>>>(xt1, Wr_mt1, b_mt1, aggt, invt, xt2, nt);

    // classifier
    edge_dot_kernel<<<gridEL16, TB>>>(xt2, xm2, el_src, el_dst, out, EL);
}

// round 7
// speedup vs baseline: 1.7093x; 1.7093x over previous
#include <cuda_runtime.h>
#include <cuda_bf16.h>
#include <mma.h>
#include <cstdint>
#include <cstddef>

using namespace nvcuda;

// Problem dims (fixed by dataset)
#define NTC 400000
#define NMC 40000
#define CH  64
#define FT  384

// ---------------- scratch (static __device__ — no allocations) ----------------
__device__ float g_xt0[(size_t)NTC * CH];
__device__ float g_xt1[(size_t)NTC * CH];
__device__ float g_xt2[(size_t)NTC * CH];
__device__ float g_aggt[(size_t)NTC * CH];
__device__ float g_xm0[(size_t)NMC * CH];
__device__ float g_xm1[(size_t)NMC * CH];
__device__ float g_xm2[(size_t)NMC * CH];
__device__ float g_aggm[(size_t)NMC * CH];
__device__ float g_ym[(size_t)NMC * CH];
__device__ int   g_cnt_t[NTC];
__device__ int   g_cnt_m[NMC];
__device__ float g_inv_t[NTC];
__device__ float g_inv_m[NMC];

// ---------------- packed f32x2 FMA ----------------
union F2U { float2 f; unsigned long long u; };
__device__ __forceinline__ float2 ffma2(float2 a, float2 b, float2 c) {
    F2U A, B, Cc, D;
    A.f = a; B.f = b; Cc.f = c;
    asm("fma.rn.f32x2 %0, %1, %2, %3;" : "=l"(D.u) : "l"(A.u), "l"(B.u), "l"(Cc.u));
    return D.f;
}

// ---------------- degree / recip ----------------
__global__ void degree_kernel(const int* __restrict__ esrc, const int* __restrict__ edst, int E) {
    int t = blockIdx.x * blockDim.x + threadIdx.x;
    if (t < E) {
        atomicAdd(&g_cnt_t[esrc[t]], 1);
        atomicAdd(&g_cnt_m[edst[t]], 1);
    }
}

__global__ void recip_kernel(const int* __restrict__ cnt, float* __restrict__ inv, int n) {
    int t = blockIdx.x * blockDim.x + threadIdx.x;
    if (t < n) inv[t] = 1.0f / fmaxf((float)cnt[t], 1.0f);
}

// ---------------- mentor encoder: x_m0 = emb_m[mentor_id] ----------------
__global__ void gather_rows_kernel(const float* __restrict__ src, const int* __restrict__ ids,
                                   float* __restrict__ out, int n) {
    int t = blockIdx.x * blockDim.x + threadIdx.x;
    int e = t >> 4;
    if (e >= n) return;
    int c4 = (t & 15) << 2;
    int id = __ldg(&ids[e]);
    float4 v = *reinterpret_cast<const float4*>(&src[(size_t)id * CH + c4]);
    *reinterpret_cast<float4*>(&out[(size_t)e * CH + c4]) = v;
}

// ---------------- edge scatter-add ----------------
__global__ void scatter_kernel(const float* __restrict__ feat, const int* __restrict__ gidx,
                               const int* __restrict__ sidx, float* __restrict__ agg, int E) {
    int t = blockIdx.x * blockDim.x + threadIdx.x;
    int e = t >> 4;
    if (e >= E) return;
    int c4 = (t & 15) << 2;
    int s = __ldg(&gidx[e]);
    int d = __ldg(&sidx[e]);
    float4 v = *reinterpret_cast<const float4*>(&feat[(size_t)s * CH + c4]);
    float* p = &agg[(size_t)d * CH + c4];
    asm volatile("red.global.add.v4.f32 [%0], {%1, %2, %3, %4};"
                 :: "l"(p), "f"(v.x), "f"(v.y), "f"(v.z), "f"(v.w) : "memory");
}

// ============================================================================
// wmma bf16-split encoder: out[128,64] = X[128,384] @ W[64,384]^T + b + emb[id]
// Split fp32 -> bf16 hi + bf16 lo(residual); 3 mma terms (hh, hl, lh) per tile.
// 256 threads = 8 warps, warp (r,c) grid 4x2, 32x32 output tile per warp.
// Grid is exact (NTC % 128 == 0) — no bounds checks.
// ============================================================================
#define AST 40   // smem k-stride (elements), mult of 8 for wmma ldm

struct EncSmem {
    union {
        struct {
            __nv_bfloat16 Ahi[128][AST];
            __nv_bfloat16 Alo[128][AST];
            __nv_bfloat16 Bhi[64][AST];
            __nv_bfloat16 Blo[64][AST];
        } cv;
        float C[128][68];
    } u;
};

__device__ __forceinline__ void cvt_store_split(__nv_bfloat16* hi_p, __nv_bfloat16* lo_p,
                                                float4 v) {
    __nv_bfloat162 h01 = __floats2bfloat162_rn(v.x, v.y);
    __nv_bfloat162 h23 = __floats2bfloat162_rn(v.z, v.w);
    float2 f01 = __bfloat1622float2(h01);
    float2 f23 = __bfloat1622float2(h23);
    __nv_bfloat162 l01 = __floats2bfloat162_rn(v.x - f01.x, v.y - f01.y);
    __nv_bfloat162 l23 = __floats2bfloat162_rn(v.z - f23.x, v.w - f23.y);
    *reinterpret_cast<uint2*>(hi_p) = make_uint2(
        *reinterpret_cast<uint32_t*>(&h01), *reinterpret_cast<uint32_t*>(&h23));
    *reinterpret_cast<uint2*>(lo_p) = make_uint2(
        *reinterpret_cast<uint32_t*>(&l01), *reinterpret_cast<uint32_t*>(&l23));
}

__global__ __launch_bounds__(256, 2)
void encoder_wmma_kernel(const float* __restrict__ X, const float* __restrict__ W,
                         const float* __restrict__ bias, const float* __restrict__ emb,
                         const int* __restrict__ ids, float* __restrict__ out) {
    __shared__ EncSmem sm;
    int tid = threadIdx.x;
    int wid = tid >> 5;
    int warp_r = wid & 3;       // 4 row groups of 32
    int warp_c = wid >> 2;      // 2 col groups of 32
    int row0 = blockIdx.x * 128;

    wmma::fragment<wmma::accumulator, 16, 16, 16, float> acc[2][2];
#pragma unroll
    for (int i = 0; i < 2; i++)
#pragma unroll
        for (int j = 0; j < 2; j++) wmma::fill_fragment(acc[i][j], 0.0f);

    for (int ch = 0; ch < FT / 32; ch++) {
        int kt = ch * 32;
        // ---- convert X chunk 128x32 ----
#pragma unroll
        for (int j = 0; j < 4; j++) {
            int idx = tid + 256 * j;
            int r = idx >> 3, cq = (idx & 7) << 2;
            float4 v = *reinterpret_cast<const float4*>(&X[(size_t)(row0 + r) * FT + kt + cq]);
            cvt_store_split(&sm.u.cv.Ahi[r][cq], &sm.u.cv.Alo[r][cq], v);
        }
        // ---- convert W chunk 64x32 ----
#pragma unroll
        for (int j = 0; j < 2; j++) {
            int idx = tid + 256 * j;
            int r = idx >> 3, cq = (idx & 7) << 2;
            float4 v = *reinterpret_cast<const float4*>(&W[(size_t)r * FT + kt + cq]);
            cvt_store_split(&sm.u.cv.Bhi[r][cq], &sm.u.cv.Blo[r][cq], v);
        }
        __syncthreads();

#pragma unroll
        for (int kk = 0; kk < 32; kk += 16) {
            wmma::fragment<wmma::matrix_a, 16, 16, 16, __nv_bfloat16, wmma::row_major> ah[2], al[2];
            wmma::fragment<wmma::matrix_b, 16, 16, 16, __nv_bfloat16, wmma::col_major> bh[2], bl[2];
#pragma unroll
            for (int i = 0; i < 2; i++) {
                wmma::load_matrix_sync(ah[i], &sm.u.cv.Ahi[warp_r * 32 + i * 16][kk], AST);
                wmma::load_matrix_sync(al[i], &sm.u.cv.Alo[warp_r * 32 + i * 16][kk], AST);
            }
#pragma unroll
            for (int j = 0; j < 2; j++) {
                wmma::load_matrix_sync(bh[j], &sm.u.cv.Bhi[warp_c * 32 + j * 16][kk], AST);
                wmma::load_matrix_sync(bl[j], &sm.u.cv.Blo[warp_c * 32 + j * 16][kk], AST);
            }
#pragma unroll
            for (int i = 0; i < 2; i++)
#pragma unroll
                for (int j = 0; j < 2; j++) {
                    wmma::mma_sync(acc[i][j], ah[i], bh[j], acc[i][j]);
                    wmma::mma_sync(acc[i][j], ah[i], bl[j], acc[i][j]);
                    wmma::mma_sync(acc[i][j], al[i], bh[j], acc[i][j]);
                }
        }
        __syncthreads();
    }

    // ---- epilogue: frags -> smem C -> +bias +emb -> gmem ----
#pragma unroll
    for (int i = 0; i < 2; i++)
#pragma unroll
        for (int j = 0; j < 2; j++)
            wmma::store_matrix_sync(&sm.u.C[warp_r * 32 + i * 16][warp_c * 32 + j * 16],
                                    acc[i][j], 68, wmma::mem_row_major);
    __syncthreads();

    int tx = tid & 15, ty = tid >> 4;
    int c4 = tx * 4;
    float4 bv = *reinterpret_cast<const float4*>(&bias[c4]);
#pragma unroll
    for (int p = 0; p < 8; p++) {
        int r = ty + p * 16;
        int nid = __ldg(&ids[row0 + r]);
        float4 ev = *reinterpret_cast<const float4*>(&emb[(size_t)nid * CH + c4]);
        float4 o;
        o.x = sm.u.C[r][c4 + 0] + bv.x + ev.x;
        o.y = sm.u.C[r][c4 + 1] + bv.y + ev.y;
        o.z = sm.u.C[r][c4 + 2] + bv.z + ev.z;
        o.w = sm.u.C[r][c4 + 3] + bv.w + ev.w;
        *reinterpret_cast<float4*>(&out[(size_t)(row0 + r) * CH + c4]) = o;
    }
}

// ---------------- K=64 GEMM (R4 proven body): out = act(X@W^T [+b] [+agg*inv]) --
template <bool RELU, bool BIAS, bool ADDAGG>
__global__ __launch_bounds__(256)
void gemm64_kernel(const float* __restrict__ X, const float* __restrict__ W,
                   const float* __restrict__ bias,
                   const float* __restrict__ aggY, const float* __restrict__ inv,
                   float* __restrict__ out, int M) {
    __shared__ float As[32][132];
    __shared__ float Ws[32][68];
    int tid = threadIdx.x;
    int tx = tid & 15, ty = tid >> 4;
    int row0 = blockIdx.x * 128;

    float2 acc[4][4];
#pragma unroll
    for (int i = 0; i < 4; i++)
#pragma unroll
        for (int j = 0; j < 4; j++) acc[i][j] = make_float2(0.f, 0.f);

    for (int kt = 0; kt < CH; kt += 32) {
#pragma unroll
        for (int i = 0; i < 4; i++) {
            int idx = tid + 256 * i;
            int r = idx >> 3;
            int kq = (idx & 7) << 2;
            int grow = row0 + r;
            float4 v = make_float4(0.f, 0.f, 0.f, 0.f);
            if (grow < M)
                v = *reinterpret_cast<const float4*>(&X[(size_t)grow * CH + kt + kq]);
            As[kq + 0][r] = v.x; As[kq + 1][r] = v.y;
            As[kq + 2][r] = v.z; As[kq + 3][r] = v.w;
        }
#pragma unroll
        for (int i = 0; i < 2; i++) {
            int idx = tid + 256 * i;
            int c = idx >> 3;
            int kq = (idx & 7) << 2;
            float4 v = *reinterpret_cast<const float4*>(&W[(size_t)c * CH + kt + kq]);
            Ws[kq + 0][c] = v.x; Ws[kq + 1][c] = v.y;
            Ws[kq + 2][c] = v.z; Ws[kq + 3][c] = v.w;
        }
        __syncthreads();
#pragma unroll
        for (int k = 0; k < 32; k++) {
            float4 a0 = *reinterpret_cast<const float4*>(&As[k][ty * 8]);
            float4 a1 = *reinterpret_cast<const float4*>(&As[k][ty * 8 + 4]);
            float4 w  = *reinterpret_cast<const float4*>(&Ws[k][tx * 4]);
            float2 ap[4] = { {a0.x, a0.y}, {a0.z, a0.w}, {a1.x, a1.y}, {a1.z, a1.w} };
            float2 wd[4] = { {w.x, w.x}, {w.y, w.y}, {w.z, w.z}, {w.w, w.w} };
#pragma unroll
            for (int rp = 0; rp < 4; rp++)
#pragma unroll
                for (int j = 0; j < 4; j++)
                    acc[rp][j] = ffma2(ap[rp], wd[j], acc[rp][j]);
        }
        __syncthreads();
    }

    float4 bv = make_float4(0.f, 0.f, 0.f, 0.f);
    if (BIAS) bv = *reinterpret_cast<const float4*>(&bias[tx * 4]);
#pragma unroll
    for (int rp = 0; rp < 4; rp++) {
#pragma unroll
        for (int s = 0; s < 2; s++) {
            int r = row0 + ty * 8 + rp * 2 + s;
            if (r < M) {
                float4 o;
                o.x = (s ? acc[rp][0].y : acc[rp][0].x) + bv.x;
                o.y = (s ? acc[rp][1].y : acc[rp][1].x) + bv.y;
                o.z = (s ? acc[rp][2].y : acc[rp][2].x) + bv.z;
                o.w = (s ? acc[rp][3].y : acc[rp][3].x) + bv.w;
                if (ADDAGG) {
                    float sc = __ldg(&inv[r]);
                    float4 av = *reinterpret_cast<const float4*>(&aggY[(size_t)r * CH + tx * 4]);
                    o.x = fmaf(av.x, sc, o.x);
                    o.y = fmaf(av.y, sc, o.y);
                    o.z = fmaf(av.z, sc, o.z);
                    o.w = fmaf(av.w, sc, o.w);
                }
                if (RELU) {
                    o.x = fmaxf(o.x, 0.f); o.y = fmaxf(o.y, 0.f);
                    o.z = fmaxf(o.z, 0.f); o.w = fmaxf(o.w, 0.f);
                }
                *reinterpret_cast<float4*>(&out[(size_t)r * CH + tx * 4]) = o;
            }
        }
    }
}

// ---------------- mentor SAGE layer GEMM (K=128, R4 proven body) ---------------
template <bool RELU>
__global__ __launch_bounds__(256)
void sage_kernel(const float* __restrict__ Agg, const float* __restrict__ inv,
                 const float* __restrict__ Xs,
                 const float* __restrict__ Wl, const float* __restrict__ Wr,
                 const float* __restrict__ bias, float* __restrict__ out, int M) {
    __shared__ float As[32][132];
    __shared__ float Ws[32][68];
    int tid = threadIdx.x;
    int tx = tid & 15, ty = tid >> 4;
    int row0 = blockIdx.x * 128;

    float2 acc[4][4];
#pragma unroll
    for (int i = 0; i < 4; i++)
#pragma unroll
        for (int j = 0; j < 4; j++) acc[i][j] = make_float2(0.f, 0.f);

    for (int tt = 0; tt < 4; tt++) {
        const float* A  = (tt < 2) ? Agg : Xs;
        const float* Wp = (tt < 2) ? Wl  : Wr;
        bool do_scale = (tt < 2);
        int kt = (tt & 1) * 32;
#pragma unroll
        for (int i = 0; i < 4; i++) {
            int idx = tid + 256 * i;
            int r = idx >> 3;
            int kq = (idx & 7) << 2;
            int grow = row0 + r;
            float4 v = make_float4(0.f, 0.f, 0.f, 0.f);
            if (grow < M) {
                v = *reinterpret_cast<const float4*>(&A[(size_t)grow * CH + kt + kq]);
                if (do_scale) {
                    float sc = __ldg(&inv[grow]);
                    v.x *= sc; v.y *= sc; v.z *= sc; v.w *= sc;
                }
            }
            As[kq + 0][r] = v.x; As[kq + 1][r] = v.y;
            As[kq + 2][r] = v.z; As[kq + 3][r] = v.w;
        }
#pragma unroll
        for (int i = 0; i < 2; i++) {
            int idx = tid + 256 * i;
            int c = idx >> 3;
            int kq = (idx & 7) << 2;
            float4 v = *reinterpret_cast<const float4*>(&Wp[(size_t)c * CH + kt + kq]);
            Ws[kq + 0][c] = v.x; Ws[kq + 1][c] = v.y;
            Ws[kq + 2][c] = v.z; Ws[kq + 3][c] = v.w;
        }
        __syncthreads();
#pragma unroll
        for (int k = 0; k < 32; k++) {
            float4 a0 = *reinterpret_cast<const float4*>(&As[k][ty * 8]);
            float4 a1 = *reinterpret_cast<const float4*>(&As[k][ty * 8 + 4]);
            float4 w  = *reinterpret_cast<const float4*>(&Ws[k][tx * 4]);
            float2 ap[4] = { {a0.x, a0.y}, {a0.z, a0.w}, {a1.x, a1.y}, {a1.z, a1.w} };
            float2 wd[4] = { {w.x, w.x}, {w.y, w.y}, {w.z, w.z}, {w.w, w.w} };
#pragma unroll
            for (int rp = 0; rp < 4; rp++)
#pragma unroll
                for (int j = 0; j < 4; j++)
                    acc[rp][j] = ffma2(ap[rp], wd[j], acc[rp][j]);
        }
        __syncthreads();
    }

    float4 bv = *reinterpret_cast<const float4*>(&bias[tx * 4]);
#pragma unroll
    for (int rp = 0; rp < 4; rp++) {
#pragma unroll
        for (int s = 0; s < 2; s++) {
            int r = row0 + ty * 8 + rp * 2 + s;
            if (r < M) {
                float4 o;
                o.x = (s ? acc[rp][0].y : acc[rp][0].x) + bv.x;
                o.y = (s ? acc[rp][1].y : acc[rp][1].x) + bv.y;
                o.z = (s ? acc[rp][2].y : acc[rp][2].x) + bv.z;
                o.w = (s ? acc[rp][3].y : acc[rp][3].x) + bv.w;
                if (RELU) {
                    o.x = fmaxf(o.x, 0.f); o.y = fmaxf(o.y, 0.f);
                    o.z = fmaxf(o.z, 0.f); o.w = fmaxf(o.w, 0.f);
                }
                *reinterpret_cast<float4*>(&out[(size_t)r * CH + tx * 4]) = o;
            }
        }
    }
}

// ---------------- edge dot-product classifier --------------------------------
__global__ void edge_dot_kernel(const float* __restrict__ xt, const float* __restrict__ xm,
                                const int* __restrict__ es, const int* __restrict__ ed,
                                float* __restrict__ out, int E) {
    int t = blockIdx.x * blockDim.x + threadIdx.x;
    int e = t >> 4;
    if (e >= E) return;
    int c4 = (t & 15) << 2;
    int s = __ldg(&es[e]);
    int d = __ldg(&ed[e]);
    float4 a = *reinterpret_cast<const float4*>(&xt[(size_t)s * CH + c4]);
    float4 b = *reinterpret_cast<const float4*>(&xm[(size_t)d * CH + c4]);
    float p = a.x * b.x + a.y * b.y + a.z * b.z + a.w * b.w;
    p += __shfl_down_sync(0xffffffffu, p, 8);
    p += __shfl_down_sync(0xffffffffu, p, 4);
    p += __shfl_down_sync(0xffffffffu, p, 2);
    p += __shfl_down_sync(0xffffffffu, p, 1);
    if ((t & 15) == 0) out[e] = p;
}

// ---------------- launch -----------------------------------------------------
extern "C" void kernel_launch(void* const* d_in, const int* in_sizes, int n_in,
                              void* d_out, int out_size) {
    const float* x_thesis  = (const float*)d_in[0];
    const int*   thesis_id = (const int*)d_in[1];
    const int*   mentor_id = (const int*)d_in[2];
    const int*   edge_src  = (const int*)d_in[3];
    const int*   edge_dst  = (const int*)d_in[4];
    const int*   el_src    = (const int*)d_in[5];
    const int*   el_dst    = (const int*)d_in[6];
    const float* lin_W     = (const float*)d_in[7];
    const float* lin_b     = (const float*)d_in[8];
    const float* emb_t     = (const float*)d_in[9];
    const float* emb_m     = (const float*)d_in[10];
    const float* Wl_tm0    = (const float*)d_in[11];
    const float* Wr_tm0    = (const float*)d_in[12];
    const float* b_tm0     = (const float*)d_in[13];
    const float* Wl_mt0    = (const float*)d_in[14];
    const float* Wr_mt0    = (const float*)d_in[15];
    const float* b_mt0     = (const float*)d_in[16];
    const float* Wl_tm1    = (const float*)d_in[17];
    const float* Wr_tm1    = (const float*)d_in[18];
    const float* b_tm1     = (const float*)d_in[19];
    const float* Wl_mt1    = (const float*)d_in[20];
    const float* Wr_mt1    = (const float*)d_in[21];
    const float* b_mt1     = (const float*)d_in[22];
    float* out = (float*)d_out;

    int nt = in_sizes[1];
    int nm = in_sizes[2];
    int E  = in_sizes[3];
    int EL = in_sizes[5];

    void *p_xt0, *p_xt1, *p_xt2, *p_aggt, *p_xm0, *p_xm1, *p_xm2, *p_aggm, *p_ym;
    void *p_cntt, *p_cntm, *p_invt, *p_invm;
    cudaGetSymbolAddress(&p_xt0, g_xt0);   cudaGetSymbolAddress(&p_xt1, g_xt1);
    cudaGetSymbolAddress(&p_xt2, g_xt2);   cudaGetSymbolAddress(&p_aggt, g_aggt);
    cudaGetSymbolAddress(&p_xm0, g_xm0);   cudaGetSymbolAddress(&p_xm1, g_xm1);
    cudaGetSymbolAddress(&p_xm2, g_xm2);   cudaGetSymbolAddress(&p_aggm, g_aggm);
    cudaGetSymbolAddress(&p_ym, g_ym);
    cudaGetSymbolAddress(&p_cntt, g_cnt_t); cudaGetSymbolAddress(&p_cntm, g_cnt_m);
    cudaGetSymbolAddress(&p_invt, g_inv_t); cudaGetSymbolAddress(&p_invm, g_inv_m);

    float* xt0 = (float*)p_xt0; float* xt1 = (float*)p_xt1; float* xt2 = (float*)p_xt2;
    float* aggt = (float*)p_aggt;
    float* xm0 = (float*)p_xm0; float* xm1 = (float*)p_xm1; float* xm2 = (float*)p_xm2;
    float* aggm = (float*)p_aggm; float* ym = (float*)p_ym;
    int* cntt = (int*)p_cntt; int* cntm = (int*)p_cntm;
    float* invt = (float*)p_invt; float* invm = (float*)p_invm;

    const int TB = 256;
    int gridE16  = (E * 16 + TB - 1) / TB;
    int gridEL16 = (EL * 16 + TB - 1) / TB;
    int gridNT   = (nt + 127) / 128;
    int gridNM   = (nm + 127) / 128;

    // ---- exactly 5 launches before the encoder so ncu (-s 5 -c 1) captures it --
    cudaMemsetAsync(cntt, 0, (size_t)nt * sizeof(int));
    cudaMemsetAsync(cntm, 0, (size_t)nm * sizeof(int));
    degree_kernel<<<(E + TB - 1) / TB, TB>>>(edge_src, edge_dst, E);
    recip_kernel<<<(nt + TB - 1) / TB, TB>>>(cntt, invt, nt);
    recip_kernel<<<(nm + TB - 1) / TB, TB>>>(cntm, invm, nm);

    encoder_wmma_kernel<<<gridNT, TB>>>(x_thesis, lin_W, lin_b, emb_t, thesis_id, xt0);
    gather_rows_kernel<<<(nm * 16 + TB - 1) / TB, TB>>>(emb_m, mentor_id, xm0, nm);

    // ---- layer 0 ----
    gemm64_kernel<false, false, false><<<gridNM, TB>>>(xm0, Wl_mt0, nullptr, nullptr, nullptr, ym, nm);
    cudaMemsetAsync(aggm, 0, (size_t)nm * CH * sizeof(float));
    cudaMemsetAsync(aggt, 0, (size_t)nt * CH * sizeof(float));
    scatter_kernel<<<gridE16, TB>>>(xt0, edge_src, edge_dst, aggm, E);
    scatter_kernel<<<gridE16, TB>>>(ym, edge_dst, edge_src, aggt, E);
    sage_kernel<true><<<gridNM, TB>>>(aggm, invm, xm0, Wl_tm0, Wr_tm0, b_tm0, xm1, nm);
    gemm64_kernel<true, true, true><<<gridNT, TB>>>(xt0, Wr_mt0, b_mt0, aggt, invt, xt1, nt);

    // ---- layer 1 ----
    gemm64_kernel<false, false, false><<<gridNM, TB>>>(xm1, Wl_mt1, nullptr, nullptr, nullptr, ym, nm);
    cudaMemsetAsync(aggm, 0, (size_t)nm * CH * sizeof(float));
    cudaMemsetAsync(aggt, 0, (size_t)nt * CH * sizeof(float));
    scatter_kernel<<<gridE16, TB>>>(xt1, edge_src, edge_dst, aggm, E);
    scatter_kernel<<<gridE16, TB>>>(ym, edge_dst, edge_src, aggt, E);
    sage_kernel<false><<<gridNM, TB>>>(aggm, invm, xm1, Wl_tm1, Wr_tm1, b_tm1, xm2, nm);
    gemm64_kernel<false, true, true><<<gridNT, TB>>>(xt1, Wr_mt1, b_mt1, aggt, invt, xt2, nt);

    // classifier
    edge_dot_kernel<<<gridEL16, TB>>>(xt2, xm2, el_src, el_dst, out, EL);
}

// round 10
// speedup vs baseline: 1.9426x; 1.1364x over previous
#include <cuda_runtime.h>
#include <cuda_bf16.h>
#include <mma.h>
#include <cstdint>
#include <cstddef>

using namespace nvcuda;

// Problem dims (fixed by dataset)
#define NTC 400000
#define NMC 40000
#define CH  64
#define FT  384

// ---------------- scratch (static __device__ — no allocations) ----------------
__device__ float g_xt0[(size_t)NTC * CH];
__device__ float g_xt1[(size_t)NTC * CH];
__device__ float g_xt2[(size_t)NTC * CH];
__device__ float g_aggt[(size_t)NTC * CH];
__device__ float g_xm0[(size_t)NMC * CH];
__device__ float g_xm1[(size_t)NMC * CH];
__device__ float g_xm2[(size_t)NMC * CH];
__device__ float g_aggm[(size_t)NMC * CH];
__device__ float g_ym[(size_t)NMC * CH];
__device__ int   g_cnt_t[NTC];
__device__ int   g_cnt_m[NMC];
__device__ float g_inv_t[NTC];
__device__ float g_inv_m[NMC];

// ---------------- packed f32x2 FMA ----------------
union F2U { float2 f; unsigned long long u; };
__device__ __forceinline__ float2 ffma2(float2 a, float2 b, float2 c) {
    F2U A, B, Cc, D;
    A.f = a; B.f = b; Cc.f = c;
    asm("fma.rn.f32x2 %0, %1, %2, %3;" : "=l"(D.u) : "l"(A.u), "l"(B.u), "l"(Cc.u));
    return D.f;
}

// ---------------- degree / recip ----------------
__global__ void degree_kernel(const int* __restrict__ esrc, const int* __restrict__ edst, int E) {
    int t = blockIdx.x * blockDim.x + threadIdx.x;
    if (t < E) {
        atomicAdd(&g_cnt_t[esrc[t]], 1);
        atomicAdd(&g_cnt_m[edst[t]], 1);
    }
}

__global__ void recip_kernel(const int* __restrict__ cnt, float* __restrict__ inv, int n) {
    int t = blockIdx.x * blockDim.x + threadIdx.x;
    if (t < n) inv[t] = 1.0f / fmaxf((float)cnt[t], 1.0f);
}

// ---------------- mentor encoder: x_m0 = emb_m[mentor_id] ----------------
__global__ void gather_rows_kernel(const float* __restrict__ src, const int* __restrict__ ids,
                                   float* __restrict__ out, int n) {
    int t = blockIdx.x * blockDim.x + threadIdx.x;
    int e = t >> 4;
    if (e >= n) return;
    int c4 = (t & 15) << 2;
    int id = __ldg(&ids[e]);
    float4 v = *reinterpret_cast<const float4*>(&src[(size_t)id * CH + c4]);
    *reinterpret_cast<float4*>(&out[(size_t)e * CH + c4]) = v;
}

// ---------------- edge scatter-add ----------------
__global__ void scatter_kernel(const float* __restrict__ feat, const int* __restrict__ gidx,
                               const int* __restrict__ sidx, float* __restrict__ agg, int E) {
    int t = blockIdx.x * blockDim.x + threadIdx.x;
    int e = t >> 4;
    if (e >= E) return;
    int c4 = (t & 15) << 2;
    int s = __ldg(&gidx[e]);
    int d = __ldg(&sidx[e]);
    float4 v = *reinterpret_cast<const float4*>(&feat[(size_t)s * CH + c4]);
    float* p = &agg[(size_t)d * CH + c4];
    asm volatile("red.global.add.v4.f32 [%0], {%1, %2, %3, %4};"
                 :: "l"(p), "f"(v.x), "f"(v.y), "f"(v.z), "f"(v.w) : "memory");
}

// ============================================================================
// Shared wmma bf16-split machinery
// ============================================================================
#define AST 40   // smem k-stride (elements), mult of 8 for wmma ldm

struct EncSmem {
    union {
        struct {
            __nv_bfloat16 Ahi[128][AST];
            __nv_bfloat16 Alo[128][AST];
            __nv_bfloat16 Bhi[64][AST];
            __nv_bfloat16 Blo[64][AST];
        } cv;
        float C[128][68];
    } u;
};

__device__ __forceinline__ void cvt_store_split(__nv_bfloat16* hi_p, __nv_bfloat16* lo_p,
                                                float4 v) {
    __nv_bfloat162 h01 = __floats2bfloat162_rn(v.x, v.y);
    __nv_bfloat162 h23 = __floats2bfloat162_rn(v.z, v.w);
    float2 f01 = __bfloat1622float2(h01);
    float2 f23 = __bfloat1622float2(h23);
    __nv_bfloat162 l01 = __floats2bfloat162_rn(v.x - f01.x, v.y - f01.y);
    __nv_bfloat162 l23 = __floats2bfloat162_rn(v.z - f23.x, v.w - f23.y);
    *reinterpret_cast<uint2*>(hi_p) = make_uint2(
        *reinterpret_cast<uint32_t*>(&h01), *reinterpret_cast<uint32_t*>(&h23));
    *reinterpret_cast<uint2*>(lo_p) = make_uint2(
        *reinterpret_cast<uint32_t*>(&l01), *reinterpret_cast<uint32_t*>(&l23));
}

// warp computes 32x32 tile: 2x2 accumulators, 3 split terms per 16-k step
template <int NCHUNK>
__device__ __forceinline__ void wmma_chunk_mma(
    EncSmem& sm, int warp_r, int warp_c,
    wmma::fragment<wmma::accumulator, 16, 16, 16, float> (&acc)[2][2]) {
#pragma unroll
    for (int kk = 0; kk < 32; kk += 16) {
        wmma::fragment<wmma::matrix_a, 16, 16, 16, __nv_bfloat16, wmma::row_major> ah[2], al[2];
        wmma::fragment<wmma::matrix_b, 16, 16, 16, __nv_bfloat16, wmma::col_major> bh[2], bl[2];
#pragma unroll
        for (int i = 0; i < 2; i++) {
            wmma::load_matrix_sync(ah[i], &sm.u.cv.Ahi[warp_r * 32 + i * 16][kk], AST);
            wmma::load_matrix_sync(al[i], &sm.u.cv.Alo[warp_r * 32 + i * 16][kk], AST);
        }
#pragma unroll
        for (int j = 0; j < 2; j++) {
            wmma::load_matrix_sync(bh[j], &sm.u.cv.Bhi[warp_c * 32 + j * 16][kk], AST);
            wmma::load_matrix_sync(bl[j], &sm.u.cv.Blo[warp_c * 32 + j * 16][kk], AST);
        }
#pragma unroll
        for (int i = 0; i < 2; i++)
#pragma unroll
            for (int j = 0; j < 2; j++) {
                wmma::mma_sync(acc[i][j], ah[i], bh[j], acc[i][j]);
                wmma::mma_sync(acc[i][j], ah[i], bl[j], acc[i][j]);
                wmma::mma_sync(acc[i][j], al[i], bh[j], acc[i][j]);
            }
    }
}

// ============================================================================
// wmma encoder: out[128,64] = X[128,384] @ W[64,384]^T + b + emb[id]
// ============================================================================
__global__ __launch_bounds__(256, 2)
void encoder_wmma_kernel(const float* __restrict__ X, const float* __restrict__ W,
                         const float* __restrict__ bias, const float* __restrict__ emb,
                         const int* __restrict__ ids, float* __restrict__ out) {
    __shared__ EncSmem sm;
    int tid = threadIdx.x;
    int wid = tid >> 5;
    int warp_r = wid & 3;
    int warp_c = wid >> 2;
    int row0 = blockIdx.x * 128;

    wmma::fragment<wmma::accumulator, 16, 16, 16, float> acc[2][2];
#pragma unroll
    for (int i = 0; i < 2; i++)
#pragma unroll
        for (int j = 0; j < 2; j++) wmma::fill_fragment(acc[i][j], 0.0f);

    for (int ch = 0; ch < FT / 32; ch++) {
        int kt = ch * 32;
#pragma unroll
        for (int j = 0; j < 4; j++) {
            int idx = tid + 256 * j;
            int r = idx >> 3, cq = (idx & 7) << 2;
            float4 v = *reinterpret_cast<const float4*>(&X[(size_t)(row0 + r) * FT + kt + cq]);
            cvt_store_split(&sm.u.cv.Ahi[r][cq], &sm.u.cv.Alo[r][cq], v);
        }
#pragma unroll
        for (int j = 0; j < 2; j++) {
            int idx = tid + 256 * j;
            int r = idx >> 3, cq = (idx & 7) << 2;
            float4 v = *reinterpret_cast<const float4*>(&W[(size_t)r * FT + kt + cq]);
            cvt_store_split(&sm.u.cv.Bhi[r][cq], &sm.u.cv.Blo[r][cq], v);
        }
        __syncthreads();
        wmma_chunk_mma<12>(sm, warp_r, warp_c, acc);
        __syncthreads();
    }

#pragma unroll
    for (int i = 0; i < 2; i++)
#pragma unroll
        for (int j = 0; j < 2; j++)
            wmma::store_matrix_sync(&sm.u.C[warp_r * 32 + i * 16][warp_c * 32 + j * 16],
                                    acc[i][j], 68, wmma::mem_row_major);
    __syncthreads();

    int tx = tid & 15, ty = tid >> 4;
    int c4 = tx * 4;
    float4 bv = *reinterpret_cast<const float4*>(&bias[c4]);
#pragma unroll
    for (int p = 0; p < 8; p++) {
        int r = ty + p * 16;
        int nid = __ldg(&ids[row0 + r]);
        float4 ev = *reinterpret_cast<const float4*>(&emb[(size_t)nid * CH + c4]);
        float4 o;
        o.x = sm.u.C[r][c4 + 0] + bv.x + ev.x;
        o.y = sm.u.C[r][c4 + 1] + bv.y + ev.y;
        o.z = sm.u.C[r][c4 + 2] + bv.z + ev.z;
        o.w = sm.u.C[r][c4 + 3] + bv.w + ev.w;
        *reinterpret_cast<float4*>(&out[(size_t)(row0 + r) * CH + c4]) = o;
    }
}

// ============================================================================
// wmma thesis-SAGE GEMM: out[128,64] = act( X[128,64]@W[64,64]^T + agg*inv + b )
// M must be multiple of 128 (NTC is). K=64 = 2 chunks of 32.
// ============================================================================
template <bool RELU>
__global__ __launch_bounds__(256, 2)
void gemm64_wmma_kernel(const float* __restrict__ X, const float* __restrict__ W,
                        const float* __restrict__ bias,
                        const float* __restrict__ aggY, const float* __restrict__ inv,
                        float* __restrict__ out) {
    __shared__ EncSmem sm;
    int tid = threadIdx.x;
    int wid = tid >> 5;
    int warp_r = wid & 3;
    int warp_c = wid >> 2;
    int row0 = blockIdx.x * 128;

    wmma::fragment<wmma::accumulator, 16, 16, 16, float> acc[2][2];
#pragma unroll
    for (int i = 0; i < 2; i++)
#pragma unroll
        for (int j = 0; j < 2; j++) wmma::fill_fragment(acc[i][j], 0.0f);

#pragma unroll
    for (int ch = 0; ch < 2; ch++) {
        int kt = ch * 32;
#pragma unroll
        for (int j = 0; j < 4; j++) {
            int idx = tid + 256 * j;
            int r = idx >> 3, cq = (idx & 7) << 2;
            float4 v = *reinterpret_cast<const float4*>(&X[(size_t)(row0 + r) * CH + kt + cq]);
            cvt_store_split(&sm.u.cv.Ahi[r][cq], &sm.u.cv.Alo[r][cq], v);
        }
#pragma unroll
        for (int j = 0; j < 2; j++) {
            int idx = tid + 256 * j;
            int r = idx >> 3, cq = (idx & 7) << 2;
            float4 v = *reinterpret_cast<const float4*>(&W[(size_t)r * CH + kt + cq]);
            cvt_store_split(&sm.u.cv.Bhi[r][cq], &sm.u.cv.Blo[r][cq], v);
        }
        __syncthreads();
        wmma_chunk_mma<2>(sm, warp_r, warp_c, acc);
        __syncthreads();
    }

#pragma unroll
    for (int i = 0; i < 2; i++)
#pragma unroll
        for (int j = 0; j < 2; j++)
            wmma::store_matrix_sync(&sm.u.C[warp_r * 32 + i * 16][warp_c * 32 + j * 16],
                                    acc[i][j], 68, wmma::mem_row_major);
    __syncthreads();

    int tx = tid & 15, ty = tid >> 4;
    int c4 = tx * 4;
    float4 bv = *reinterpret_cast<const float4*>(&bias[c4]);
#pragma unroll
    for (int p = 0; p < 8; p++) {
        int r = ty + p * 16;
        int gr = row0 + r;
        float sc = __ldg(&inv[gr]);
        float4 av = *reinterpret_cast<const float4*>(&aggY[(size_t)gr * CH + c4]);
        float4 o;
        o.x = fmaf(av.x, sc, sm.u.C[r][c4 + 0] + bv.x);
        o.y = fmaf(av.y, sc, sm.u.C[r][c4 + 1] + bv.y);
        o.z = fmaf(av.z, sc, sm.u.C[r][c4 + 2] + bv.z);
        o.w = fmaf(av.w, sc, sm.u.C[r][c4 + 3] + bv.w);
        if (RELU) {
            o.x = fmaxf(o.x, 0.f); o.y = fmaxf(o.y, 0.f);
            o.z = fmaxf(o.z, 0.f); o.w = fmaxf(o.w, 0.f);
        }
        *reinterpret_cast<float4*>(&out[(size_t)gr * CH + c4]) = o;
    }
}

// ---------------- K=64 FFMA2 GEMM (mentor-side, R4 proven body) ----------------
template <bool RELU, bool BIAS, bool ADDAGG>
__global__ __launch_bounds__(256)
void gemm64_kernel(const float* __restrict__ X, const float* __restrict__ W,
                   const float* __restrict__ bias,
                   const float* __restrict__ aggY, const float* __restrict__ inv,
                   float* __restrict__ out, int M) {
    __shared__ float As[32][132];
    __shared__ float Ws[32][68];
    int tid = threadIdx.x;
    int tx = tid & 15, ty = tid >> 4;
    int row0 = blockIdx.x * 128;

    float2 acc[4][4];
#pragma unroll
    for (int i = 0; i < 4; i++)
#pragma unroll
        for (int j = 0; j < 4; j++) acc[i][j] = make_float2(0.f, 0.f);

    for (int kt = 0; kt < CH; kt += 32) {
#pragma unroll
        for (int i = 0; i < 4; i++) {
            int idx = tid + 256 * i;
            int r = idx >> 3;
            int kq = (idx & 7) << 2;
            int grow = row0 + r;
            float4 v = make_float4(0.f, 0.f, 0.f, 0.f);
            if (grow < M)
                v = *reinterpret_cast<const float4*>(&X[(size_t)grow * CH + kt + kq]);
            As[kq + 0][r] = v.x; As[kq + 1][r] = v.y;
            As[kq + 2][r] = v.z; As[kq + 3][r] = v.w;
        }
#pragma unroll
        for (int i = 0; i < 2; i++) {
            int idx = tid + 256 * i;
            int c = idx >> 3;
            int kq = (idx & 7) << 2;
            float4 v = *reinterpret_cast<const float4*>(&W[(size_t)c * CH + kt + kq]);
            Ws[kq + 0][c] = v.x; Ws[kq + 1][c] = v.y;
            Ws[kq + 2][c] = v.z; Ws[kq + 3][c] = v.w;
        }
        __syncthreads();
#pragma unroll
        for (int k = 0; k < 32; k++) {
            float4 a0 = *reinterpret_cast<const float4*>(&As[k][ty * 8]);
            float4 a1 = *reinterpret_cast<const float4*>(&As[k][ty * 8 + 4]);
            float4 w  = *reinterpret_cast<const float4*>(&Ws[k][tx * 4]);
            float2 ap[4] = { {a0.x, a0.y}, {a0.z, a0.w}, {a1.x, a1.y}, {a1.z, a1.w} };
            float2 wd[4] = { {w.x, w.x}, {w.y, w.y}, {w.z, w.z}, {w.w, w.w} };
#pragma unroll
            for (int rp = 0; rp < 4; rp++)
#pragma unroll
                for (int j = 0; j < 4; j++)
                    acc[rp][j] = ffma2(ap[rp], wd[j], acc[rp][j]);
        }
        __syncthreads();
    }

    float4 bv = make_float4(0.f, 0.f, 0.f, 0.f);
    if (BIAS) bv = *reinterpret_cast<const float4*>(&bias[tx * 4]);
#pragma unroll
    for (int rp = 0; rp < 4; rp++) {
#pragma unroll
        for (int s = 0; s < 2; s++) {
            int r = row0 + ty * 8 + rp * 2 + s;
            if (r < M) {
                float4 o;
                o.x = (s ? acc[rp][0].y : acc[rp][0].x) + bv.x;
                o.y = (s ? acc[rp][1].y : acc[rp][1].x) + bv.y;
                o.z = (s ? acc[rp][2].y : acc[rp][2].x) + bv.z;
                o.w = (s ? acc[rp][3].y : acc[rp][3].x) + bv.w;
                if (ADDAGG) {
                    float sc = __ldg(&inv[r]);
                    float4 av = *reinterpret_cast<const float4*>(&aggY[(size_t)r * CH + tx * 4]);
                    o.x = fmaf(av.x, sc, o.x);
                    o.y = fmaf(av.y, sc, o.y);
                    o.z = fmaf(av.z, sc, o.z);
                    o.w = fmaf(av.w, sc, o.w);
                }
                if (RELU) {
                    o.x = fmaxf(o.x, 0.f); o.y = fmaxf(o.y, 0.f);
                    o.z = fmaxf(o.z, 0.f); o.w = fmaxf(o.w, 0.f);
                }
                *reinterpret_cast<float4*>(&out[(size_t)r * CH + tx * 4]) = o;
            }
        }
    }
}

// ---------------- mentor SAGE layer GEMM (K=128, R4 proven body) ---------------
template <bool RELU>
__global__ __launch_bounds__(256)
void sage_kernel(const float* __restrict__ Agg, const float* __restrict__ inv,
                 const float* __restrict__ Xs,
                 const float* __restrict__ Wl, const float* __restrict__ Wr,
                 const float* __restrict__ bias, float* __restrict__ out, int M) {
    __shared__ float As[32][132];
    __shared__ float Ws[32][68];
    int tid = threadIdx.x;
    int tx = tid & 15, ty = tid >> 4;
    int row0 = blockIdx.x * 128;

    float2 acc[4][4];
#pragma unroll
    for (int i = 0; i < 4; i++)
#pragma unroll
        for (int j = 0; j < 4; j++) acc[i][j] = make_float2(0.f, 0.f);

    for (int tt = 0; tt < 4; tt++) {
        const float* A  = (tt < 2) ? Agg : Xs;
        const float* Wp = (tt < 2) ? Wl  : Wr;
        bool do_scale = (tt < 2);
        int kt = (tt & 1) * 32;
#pragma unroll
        for (int i = 0; i < 4; i++) {
            int idx = tid + 256 * i;
            int r = idx >> 3;
            int kq = (idx & 7) << 2;
            int grow = row0 + r;
            float4 v = make_float4(0.f, 0.f, 0.f, 0.f);
            if (grow < M) {
                v = *reinterpret_cast<const float4*>(&A[(size_t)grow * CH + kt + kq]);
                if (do_scale) {
                    float sc = __ldg(&inv[grow]);
                    v.x *= sc; v.y *= sc; v.z *= sc; v.w *= sc;
                }
            }
            As[kq + 0][r] = v.x; As[kq + 1][r] = v.y;
            As[kq + 2][r] = v.z; As[kq + 3][r] = v.w;
        }
#pragma unroll
        for (int i = 0; i < 2; i++) {
            int idx = tid + 256 * i;
            int c = idx >> 3;
            int kq = (idx & 7) << 2;
            float4 v = *reinterpret_cast<const float4*>(&Wp[(size_t)c * CH + kt + kq]);
            Ws[kq + 0][c] = v.x; Ws[kq + 1][c] = v.y;
            Ws[kq + 2][c] = v.z; Ws[kq + 3][c] = v.w;
        }
        __syncthreads();
#pragma unroll
        for (int k = 0; k < 32; k++) {
            float4 a0 = *reinterpret_cast<const float4*>(&As[k][ty * 8]);
            float4 a1 = *reinterpret_cast<const float4*>(&As[k][ty * 8 + 4]);
            float4 w  = *reinterpret_cast<const float4*>(&Ws[k][tx * 4]);
            float2 ap[4] = { {a0.x, a0.y}, {a0.z, a0.w}, {a1.x, a1.y}, {a1.z, a1.w} };
            float2 wd[4] = { {w.x, w.x}, {w.y, w.y}, {w.z, w.z}, {w.w, w.w} };
#pragma unroll
            for (int rp = 0; rp < 4; rp++)
#pragma unroll
                for (int j = 0; j < 4; j++)
                    acc[rp][j] = ffma2(ap[rp], wd[j], acc[rp][j]);
        }
        __syncthreads();
    }

    float4 bv = *reinterpret_cast<const float4*>(&bias[tx * 4]);
#pragma unroll
    for (int rp = 0; rp < 4; rp++) {
#pragma unroll
        for (int s = 0; s < 2; s++) {
            int r = row0 + ty * 8 + rp * 2 + s;
            if (r < M) {
                float4 o;
                o.x = (s ? acc[rp][0].y : acc[rp][0].x) + bv.x;
                o.y = (s ? acc[rp][1].y : acc[rp][1].x) + bv.y;
                o.z = (s ? acc[rp][2].y : acc[rp][2].x) + bv.z;
                o.w = (s ? acc[rp][3].y : acc[rp][3].x) + bv.w;
                if (RELU) {
                    o.x = fmaxf(o.x, 0.f); o.y = fmaxf(o.y, 0.f);
                    o.z = fmaxf(o.z, 0.f); o.w = fmaxf(o.w, 0.f);
                }
                *reinterpret_cast<float4*>(&out[(size_t)r * CH + tx * 4]) = o;
            }
        }
    }
}

// ---------------- edge dot-product classifier --------------------------------
__global__ void edge_dot_kernel(const float* __restrict__ xt, const float* __restrict__ xm,
                                const int* __restrict__ es, const int* __restrict__ ed,
                                float* __restrict__ out, int E) {
    int t = blockIdx.x * blockDim.x + threadIdx.x;
    int e = t >> 4;
    if (e >= E) return;
    int c4 = (t & 15) << 2;
    int s = __ldg(&es[e]);
    int d = __ldg(&ed[e]);
    float4 a = *reinterpret_cast<const float4*>(&xt[(size_t)s * CH + c4]);
    float4 b = *reinterpret_cast<const float4*>(&xm[(size_t)d * CH + c4]);
    float p = a.x * b.x + a.y * b.y + a.z * b.z + a.w * b.w;
    p += __shfl_down_sync(0xffffffffu, p, 8);
    p += __shfl_down_sync(0xffffffffu, p, 4);
    p += __shfl_down_sync(0xffffffffu, p, 2);
    p += __shfl_down_sync(0xffffffffu, p, 1);
    if ((t & 15) == 0) out[e] = p;
}

// ---------------- launch -----------------------------------------------------
extern "C" void kernel_launch(void* const* d_in, const int* in_sizes, int n_in,
                              void* d_out, int out_size) {
    const float* x_thesis  = (const float*)d_in[0];
    const int*   thesis_id = (const int*)d_in[1];
    const int*   mentor_id = (const int*)d_in[2];
    const int*   edge_src  = (const int*)d_in[3];
    const int*   edge_dst  = (const int*)d_in[4];
    const int*   el_src    = (const int*)d_in[5];
    const int*   el_dst    = (const int*)d_in[6];
    const float* lin_W     = (const float*)d_in[7];
    const float* lin_b     = (const float*)d_in[8];
    const float* emb_t     = (const float*)d_in[9];
    const float* emb_m     = (const float*)d_in[10];
    const float* Wl_tm0    = (const float*)d_in[11];
    const float* Wr_tm0    = (const float*)d_in[12];
    const float* b_tm0     = (const float*)d_in[13];
    const float* Wl_mt0    = (const float*)d_in[14];
    const float* Wr_mt0    = (const float*)d_in[15];
    const float* b_mt0     = (const float*)d_in[16];
    const float* Wl_tm1    = (const float*)d_in[17];
    const float* Wr_tm1    = (const float*)d_in[18];
    const float* b_tm1     = (const float*)d_in[19];
    const float* Wl_mt1    = (const float*)d_in[20];
    const float* Wr_mt1    = (const float*)d_in[21];
    const float* b_mt1     = (const float*)d_in[22];
    float* out = (float*)d_out;

    int nt = in_sizes[1];
    int nm = in_sizes[2];
    int E  = in_sizes[3];
    int EL = in_sizes[5];

    void *p_xt0, *p_xt1, *p_xt2, *p_aggt, *p_xm0, *p_xm1, *p_xm2, *p_aggm, *p_ym;
    void *p_cntt, *p_cntm, *p_invt, *p_invm;
    cudaGetSymbolAddress(&p_xt0, g_xt0);   cudaGetSymbolAddress(&p_xt1, g_xt1);
    cudaGetSymbolAddress(&p_xt2, g_xt2);   cudaGetSymbolAddress(&p_aggt, g_aggt);
    cudaGetSymbolAddress(&p_xm0, g_xm0);   cudaGetSymbolAddress(&p_xm1, g_xm1);
    cudaGetSymbolAddress(&p_xm2, g_xm2);   cudaGetSymbolAddress(&p_aggm, g_aggm);
    cudaGetSymbolAddress(&p_ym, g_ym);
    cudaGetSymbolAddress(&p_cntt, g_cnt_t); cudaGetSymbolAddress(&p_cntm, g_cnt_m);
    cudaGetSymbolAddress(&p_invt, g_inv_t); cudaGetSymbolAddress(&p_invm, g_inv_m);

    float* xt0 = (float*)p_xt0; float* xt1 = (float*)p_xt1; float* xt2 = (float*)p_xt2;
    float* aggt = (float*)p_aggt;
    float* xm0 = (float*)p_xm0; float* xm1 = (float*)p_xm1; float* xm2 = (float*)p_xm2;
    float* aggm = (float*)p_aggm; float* ym = (float*)p_ym;
    int* cntt = (int*)p_cntt; int* cntm = (int*)p_cntm;
    float* invt = (float*)p_invt; float* invm = (float*)p_invm;

    const int TB = 256;
    int gridE16  = (E * 16 + TB - 1) / TB;
    int gridEL16 = (EL * 16 + TB - 1) / TB;
    int gridNT   = (nt + 127) / 128;
    int gridNM   = (nm + 127) / 128;

    // ---- exactly 5 launches before the encoder so ncu (-s 5 -c 1) captures it --
    cudaMemsetAsync(cntt, 0, (size_t)nt * sizeof(int));
    cudaMemsetAsync(cntm, 0, (size_t)nm * sizeof(int));
    degree_kernel<<<(E + TB - 1) / TB, TB>>>(edge_src, edge_dst, E);
    recip_kernel<<<(nt + TB - 1) / TB, TB>>>(cntt, invt, nt);
    recip_kernel<<<(nm + TB - 1) / TB, TB>>>(cntm, invm, nm);

    encoder_wmma_kernel<<<gridNT, TB>>>(x_thesis, lin_W, lin_b, emb_t, thesis_id, xt0);
    gather_rows_kernel<<<(nm * 16 + TB - 1) / TB, TB>>>(emb_m, mentor_id, xm0, nm);

    // ---- layer 0 ----
    gemm64_kernel<false, false, false><<<gridNM, TB>>>(xm0, Wl_mt0, nullptr, nullptr, nullptr, ym, nm);
    cudaMemsetAsync(aggm, 0, (size_t)nm * CH * sizeof(float));
    cudaMemsetAsync(aggt, 0, (size_t)nt * CH * sizeof(float));
    scatter_kernel<<<gridE16, TB>>>(xt0, edge_src, edge_dst, aggm, E);
    scatter_kernel<<<gridE16, TB>>>(ym, edge_dst, edge_src, aggt, E);
    sage_kernel<true><<<gridNM, TB>>>(aggm, invm, xm0, Wl_tm0, Wr_tm0, b_tm0, xm1, nm);
    gemm64_wmma_kernel<true><<<gridNT, TB>>>(xt0, Wr_mt0, b_mt0, aggt, invt, xt1);

    // ---- layer 1 ----
    gemm64_kernel<false, false, false><<<gridNM, TB>>>(xm1, Wl_mt1, nullptr, nullptr, nullptr, ym, nm);
    cudaMemsetAsync(aggm, 0, (size_t)nm * CH * sizeof(float));
    cudaMemsetAsync(aggt, 0, (size_t)nt * CH * sizeof(float));
    scatter_kernel<<<gridE16, TB>>>(xt1, edge_src, edge_dst, aggm, E);
    scatter_kernel<<<gridE16, TB>>>(ym, edge_dst, edge_src, aggt, E);
    sage_kernel<false><<<gridNM, TB>>>(aggm, invm, xm1, Wl_tm1, Wr_tm1, b_tm1, xm2, nm);
    gemm64_wmma_kernel<false><<<gridNT, TB>>>(xt1, Wr_mt1, b_mt1, aggt, invt, xt2);

    // classifier
    edge_dot_kernel<<<gridEL16, TB>>>(xt2, xm2, el_src, el_dst, out, EL);
}

// round 11
// speedup vs baseline: 1.9688x; 1.0135x over previous
#include <cuda_runtime.h>
#include <cuda_bf16.h>
#include <mma.h>
#include <cstdint>
#include <cstddef>

using namespace nvcuda;

// Problem dims (fixed by dataset)
#define NTC 400000
#define NMC 40000
#define CH  64
#define FT  384

// ---------------- scratch (static __device__ — no allocations) ----------------
__device__ float g_xt0[(size_t)NTC * CH];
__device__ float g_xt1[(size_t)NTC * CH];
__device__ float g_xt2[(size_t)NTC * CH];
__device__ float g_aggt[(size_t)NTC * CH];
__device__ float g_xm0[(size_t)NMC * CH];
__device__ float g_xm1[(size_t)NMC * CH];
__device__ float g_xm2[(size_t)NMC * CH];
__device__ float g_aggm[(size_t)NMC * CH];
__device__ float g_ym[(size_t)NMC * CH];
__device__ int   g_cnt_t[NTC];
__device__ int   g_cnt_m[NMC];
__device__ float g_inv_t[NTC];
__device__ float g_inv_m[NMC];

// ---------------- packed f32x2 FMA ----------------
union F2U { float2 f; unsigned long long u; };
__device__ __forceinline__ float2 ffma2(float2 a, float2 b, float2 c) {
    F2U A, B, Cc, D;
    A.f = a; B.f = b; Cc.f = c;
    asm("fma.rn.f32x2 %0, %1, %2, %3;" : "=l"(D.u) : "l"(A.u), "l"(B.u), "l"(Cc.u));
    return D.f;
}

__device__ __forceinline__ uint32_t smem_u32(const void* p) {
    uint32_t a;
    asm("{ .reg .u64 t; cvta.to.shared.u64 t, %1; cvt.u32.u64 %0, t; }" : "=r"(a) : "l"(p));
    return a;
}
__device__ __forceinline__ void cp_async16(uint32_t dst, const void* src) {
    asm volatile("cp.async.cg.shared.global [%0], [%1], 16;" :: "r"(dst), "l"(src));
}

// ---------------- degree / recip ----------------
__global__ void degree_kernel(const int* __restrict__ esrc, const int* __restrict__ edst, int E) {
    int t = blockIdx.x * blockDim.x + threadIdx.x;
    if (t < E) {
        atomicAdd(&g_cnt_t[esrc[t]], 1);
        atomicAdd(&g_cnt_m[edst[t]], 1);
    }
}

__global__ void recip_kernel(const int* __restrict__ cnt, float* __restrict__ inv, int n) {
    int t = blockIdx.x * blockDim.x + threadIdx.x;
    if (t < n) inv[t] = 1.0f / fmaxf((float)cnt[t], 1.0f);
}

// ---------------- mentor encoder: x_m0 = emb_m[mentor_id] ----------------
__global__ void gather_rows_kernel(const float* __restrict__ src, const int* __restrict__ ids,
                                   float* __restrict__ out, int n) {
    int t = blockIdx.x * blockDim.x + threadIdx.x;
    int e = t >> 4;
    if (e >= n) return;
    int c4 = (t & 15) << 2;
    int id = __ldg(&ids[e]);
    float4 v = *reinterpret_cast<const float4*>(&src[(size_t)id * CH + c4]);
    *reinterpret_cast<float4*>(&out[(size_t)e * CH + c4]) = v;
}

// ---------------- edge scatter-add ----------------
__global__ void scatter_kernel(const float* __restrict__ feat, const int* __restrict__ gidx,
                               const int* __restrict__ sidx, float* __restrict__ agg, int E) {
    int t = blockIdx.x * blockDim.x + threadIdx.x;
    int e = t >> 4;
    if (e >= E) return;
    int c4 = (t & 15) << 2;
    int s = __ldg(&gidx[e]);
    int d = __ldg(&sidx[e]);
    float4 v = *reinterpret_cast<const float4*>(&feat[(size_t)s * CH + c4]);
    float* p = &agg[(size_t)d * CH + c4];
    asm volatile("red.global.add.v4.f32 [%0], {%1, %2, %3, %4};"
                 :: "l"(p), "f"(v.x), "f"(v.y), "f"(v.z), "f"(v.w) : "memory");
}

// ============================================================================
// Shared wmma bf16-split machinery
// ============================================================================
#define AST 40   // smem k-stride (elements), mult of 8 for wmma ldm

struct CvBufs {
    __nv_bfloat16 Ahi[128][AST];
    __nv_bfloat16 Alo[128][AST];
    __nv_bfloat16 Bhi[64][AST];
    __nv_bfloat16 Blo[64][AST];
};

// Pipelined encoder smem: fp32 stage (double-buffered) unioned with epilogue C
#define XSTR 36   // stage row stride in floats (16B-aligned rows, bank-skewed)
struct EncSmemP {
    union {
        struct {
            float Xs[2][128][XSTR];
            float Ws[2][64][XSTR];
        } st;
        float C[128][68];
    } a;
    CvBufs cv;
};

// gemm64 smem (non-pipelined): convert buffers unioned with epilogue C
struct G64Smem {
    union {
        CvBufs cv;
        float C[128][68];
    } u;
};

__device__ __forceinline__ void cvt_store_split(__nv_bfloat16* hi_p, __nv_bfloat16* lo_p,
                                                float4 v) {
    __nv_bfloat162 h01 = __floats2bfloat162_rn(v.x, v.y);
    __nv_bfloat162 h23 = __floats2bfloat162_rn(v.z, v.w);
    float2 f01 = __bfloat1622float2(h01);
    float2 f23 = __bfloat1622float2(h23);
    __nv_bfloat162 l01 = __floats2bfloat162_rn(v.x - f01.x, v.y - f01.y);
    __nv_bfloat162 l23 = __floats2bfloat162_rn(v.z - f23.x, v.w - f23.y);
    *reinterpret_cast<uint2*>(hi_p) = make_uint2(
        *reinterpret_cast<uint32_t*>(&h01), *reinterpret_cast<uint32_t*>(&h23));
    *reinterpret_cast<uint2*>(lo_p) = make_uint2(
        *reinterpret_cast<uint32_t*>(&l01), *reinterpret_cast<uint32_t*>(&l23));
}

// warp computes 32x32 tile: 2x2 accumulators, 3 split terms per 16-k step
__device__ __forceinline__ void wmma_chunk_mma(
    CvBufs& cv, int warp_r, int warp_c,
    wmma::fragment<wmma::accumulator, 16, 16, 16, float> (&acc)[2][2]) {
#pragma unroll
    for (int kk = 0; kk < 32; kk += 16) {
        wmma::fragment<wmma::matrix_a, 16, 16, 16, __nv_bfloat16, wmma::row_major> ah[2], al[2];
        wmma::fragment<wmma::matrix_b, 16, 16, 16, __nv_bfloat16, wmma::col_major> bh[2], bl[2];
#pragma unroll
        for (int i = 0; i < 2; i++) {
            wmma::load_matrix_sync(ah[i], &cv.Ahi[warp_r * 32 + i * 16][kk], AST);
            wmma::load_matrix_sync(al[i], &cv.Alo[warp_r * 32 + i * 16][kk], AST);
        }
#pragma unroll
        for (int j = 0; j < 2; j++) {
            wmma::load_matrix_sync(bh[j], &cv.Bhi[warp_c * 32 + j * 16][kk], AST);
            wmma::load_matrix_sync(bl[j], &cv.Blo[warp_c * 32 + j * 16][kk], AST);
        }
#pragma unroll
        for (int i = 0; i < 2; i++)
#pragma unroll
            for (int j = 0; j < 2; j++) {
                wmma::mma_sync(acc[i][j], ah[i], bh[j], acc[i][j]);
                wmma::mma_sync(acc[i][j], ah[i], bl[j], acc[i][j]);
                wmma::mma_sync(acc[i][j], al[i], bh[j], acc[i][j]);
            }
    }
}

// ============================================================================
// Pipelined wmma encoder: out[128,64] = X[128,384] @ W[64,384]^T + b + emb[id]
// cp.async double-buffered fp32 stage hides DRAM latency behind mma.
// ============================================================================
#define ENC_NC (FT / 32)
#define ENC_SMEM ((int)sizeof(EncSmemP))

__global__ __launch_bounds__(256, 2)
void encoder_wmma_kernel(const float* __restrict__ X, const float* __restrict__ W,
                         const float* __restrict__ bias, const float* __restrict__ emb,
                         const int* __restrict__ ids, float* __restrict__ out) {
    extern __shared__ char smraw[];
    EncSmemP& sm = *reinterpret_cast<EncSmemP*>(smraw);
    int tid = threadIdx.x;
    int wid = tid >> 5;
    int warp_r = wid & 3;
    int warp_c = wid >> 2;
    int row0 = blockIdx.x * 128;

    wmma::fragment<wmma::accumulator, 16, 16, 16, float> acc[2][2];
#pragma unroll
    for (int i = 0; i < 2; i++)
#pragma unroll
        for (int j = 0; j < 2; j++) wmma::fill_fragment(acc[i][j], 0.0f);

    int r_x = tid >> 3;                 // convert/stage row base (X: +0,+32,+64,+96)
    int cq  = (tid & 7) << 2;           // 0..28

    // ---- prologue: stage chunk 0 ----
    {
#pragma unroll
        for (int j = 0; j < 4; j++) {
            int r = r_x + 32 * j;
            cp_async16(smem_u32(&sm.a.st.Xs[0][r][cq]), &X[(size_t)(row0 + r) * FT + cq]);
        }
#pragma unroll
        for (int j = 0; j < 2; j++) {
            int r = r_x + 32 * j;
            cp_async16(smem_u32(&sm.a.st.Ws[0][r][cq]), &W[(size_t)r * FT + cq]);
        }
        asm volatile("cp.async.commit_group;");
    }

    for (int ch = 0; ch < ENC_NC; ch++) {
        int buf = ch & 1;
        bool more = (ch + 1 < ENC_NC);
        if (more) {
            int kt = (ch + 1) * 32;
#pragma unroll
            for (int j = 0; j < 4; j++) {
                int r = r_x + 32 * j;
                cp_async16(smem_u32(&sm.a.st.Xs[buf ^ 1][r][cq]),
                           &X[(size_t)(row0 + r) * FT + kt + cq]);
            }
#pragma unroll
            for (int j = 0; j < 2; j++) {
                int r = r_x + 32 * j;
                cp_async16(smem_u32(&sm.a.st.Ws[buf ^ 1][r][cq]),
                           &W[(size_t)r * FT + kt + cq]);
            }
            asm volatile("cp.async.commit_group;");
            asm volatile("cp.async.wait_group 1;");
        } else {
            asm volatile("cp.async.wait_group 0;");
        }
        __syncthreads();   // prev mma done reading cv; this thread's stage[buf] ready
#pragma unroll
        for (int j = 0; j < 4; j++) {
            int r = r_x + 32 * j;
            float4 v = *reinterpret_cast<const float4*>(&sm.a.st.Xs[buf][r][cq]);
            cvt_store_split(&sm.cv.Ahi[r][cq], &sm.cv.Alo[r][cq], v);
        }
#pragma unroll
        for (int j = 0; j < 2; j++) {
            int r = r_x + 32 * j;
            float4 v = *reinterpret_cast<const float4*>(&sm.a.st.Ws[buf][r][cq]);
            cvt_store_split(&sm.cv.Bhi[r][cq], &sm.cv.Blo[r][cq], v);
        }
        __syncthreads();   // cv ready
        wmma_chunk_mma(sm.cv, warp_r, warp_c, acc);
    }
    __syncthreads();       // all mma reads done before C overlays stage

#pragma unroll
    for (int i = 0; i < 2; i++)
#pragma unroll
        for (int j = 0; j < 2; j++)
            wmma::store_matrix_sync(&sm.a.C[warp_r * 32 + i * 16][warp_c * 32 + j * 16],
                                    acc[i][j], 68, wmma::mem_row_major);
    __syncthreads();

    int tx = tid & 15, ty = tid >> 4;
    int c4 = tx * 4;
    float4 bv = *reinterpret_cast<const float4*>(&bias[c4]);
#pragma unroll
    for (int p = 0; p < 8; p++) {
        int r = ty + p * 16;
        int nid = __ldg(&ids[row0 + r]);
        float4 ev = *reinterpret_cast<const float4*>(&emb[(size_t)nid * CH + c4]);
        float4 o;
        o.x = sm.a.C[r][c4 + 0] + bv.x + ev.x;
        o.y = sm.a.C[r][c4 + 1] + bv.y + ev.y;
        o.z = sm.a.C[r][c4 + 2] + bv.z + ev.z;
        o.w = sm.a.C[r][c4 + 3] + bv.w + ev.w;
        *reinterpret_cast<float4*>(&out[(size_t)(row0 + r) * CH + c4]) = o;
    }
}

// ============================================================================
// wmma thesis-SAGE GEMM: out[128,64] = act( X[128,64]@W[64,64]^T + agg*inv + b )
// ============================================================================
template <bool RELU>
__global__ __launch_bounds__(256, 2)
void gemm64_wmma_kernel(const float* __restrict__ X, const float* __restrict__ W,
                        const float* __restrict__ bias,
                        const float* __restrict__ aggY, const float* __restrict__ inv,
                        float* __restrict__ out) {
    __shared__ G64Smem sm;
    int tid = threadIdx.x;
    int wid = tid >> 5;
    int warp_r = wid & 3;
    int warp_c = wid >> 2;
    int row0 = blockIdx.x * 128;

    wmma::fragment<wmma::accumulator, 16, 16, 16, float> acc[2][2];
#pragma unroll
    for (int i = 0; i < 2; i++)
#pragma unroll
        for (int j = 0; j < 2; j++) wmma::fill_fragment(acc[i][j], 0.0f);

#pragma unroll
    for (int ch = 0; ch < 2; ch++) {
        int kt = ch * 32;
#pragma unroll
        for (int j = 0; j < 4; j++) {
            int idx = tid + 256 * j;
            int r = idx >> 3, cq = (idx & 7) << 2;
            float4 v = *reinterpret_cast<const float4*>(&X[(size_t)(row0 + r) * CH + kt + cq]);
            cvt_store_split(&sm.u.cv.Ahi[r][cq], &sm.u.cv.Alo[r][cq], v);
        }
#pragma unroll
        for (int j = 0; j < 2; j++) {
            int idx = tid + 256 * j;
            int r = idx >> 3, cq = (idx & 7) << 2;
            float4 v = *reinterpret_cast<const float4*>(&W[(size_t)r * CH + kt + cq]);
            cvt_store_split(&sm.u.cv.Bhi[r][cq], &sm.u.cv.Blo[r][cq], v);
        }
        __syncthreads();
        wmma_chunk_mma(sm.u.cv, warp_r, warp_c, acc);
        __syncthreads();
    }

#pragma unroll
    for (int i = 0; i < 2; i++)
#pragma unroll
        for (int j = 0; j < 2; j++)
            wmma::store_matrix_sync(&sm.u.C[warp_r * 32 + i * 16][warp_c * 32 + j * 16],
                                    acc[i][j], 68, wmma::mem_row_major);
    __syncthreads();

    int tx = tid & 15, ty = tid >> 4;
    int c4 = tx * 4;
    float4 bv = *reinterpret_cast<const float4*>(&bias[c4]);
#pragma unroll
    for (int p = 0; p < 8; p++) {
        int r = ty + p * 16;
        int gr = row0 + r;
        float sc = __ldg(&inv[gr]);
        float4 av = *reinterpret_cast<const float4*>(&aggY[(size_t)gr * CH + c4]);
        float4 o;
        o.x = fmaf(av.x, sc, sm.u.C[r][c4 + 0] + bv.x);
        o.y = fmaf(av.y, sc, sm.u.C[r][c4 + 1] + bv.y);
        o.z = fmaf(av.z, sc, sm.u.C[r][c4 + 2] + bv.z);
        o.w = fmaf(av.w, sc, sm.u.C[r][c4 + 3] + bv.w);
        if (RELU) {
            o.x = fmaxf(o.x, 0.f); o.y = fmaxf(o.y, 0.f);
            o.z = fmaxf(o.z, 0.f); o.w = fmaxf(o.w, 0.f);
        }
        *reinterpret_cast<float4*>(&out[(size_t)gr * CH + c4]) = o;
    }
}

// ---------------- K=64 FFMA2 GEMM (mentor-side, R4 proven body) ----------------
template <bool RELU, bool BIAS, bool ADDAGG>
__global__ __launch_bounds__(256)
void gemm64_kernel(const float* __restrict__ X, const float* __restrict__ W,
                   const float* __restrict__ bias,
                   const float* __restrict__ aggY, const float* __restrict__ inv,
                   float* __restrict__ out, int M) {
    __shared__ float As[32][132];
    __shared__ float Ws[32][68];
    int tid = threadIdx.x;
    int tx = tid & 15, ty = tid >> 4;
    int row0 = blockIdx.x * 128;

    float2 acc[4][4];
#pragma unroll
    for (int i = 0; i < 4; i++)
#pragma unroll
        for (int j = 0; j < 4; j++) acc[i][j] = make_float2(0.f, 0.f);

    for (int kt = 0; kt < CH; kt += 32) {
#pragma unroll
        for (int i = 0; i < 4; i++) {
            int idx = tid + 256 * i;
            int r = idx >> 3;
            int kq = (idx & 7) << 2;
            int grow = row0 + r;
            float4 v = make_float4(0.f, 0.f, 0.f, 0.f);
            if (grow < M)
                v = *reinterpret_cast<const float4*>(&X[(size_t)grow * CH + kt + kq]);
            As[kq + 0][r] = v.x; As[kq + 1][r] = v.y;
            As[kq + 2][r] = v.z; As[kq + 3][r] = v.w;
        }
#pragma unroll
        for (int i = 0; i < 2; i++) {
            int idx = tid + 256 * i;
            int c = idx >> 3;
            int kq = (idx & 7) << 2;
            float4 v = *reinterpret_cast<const float4*>(&W[(size_t)c * CH + kt + kq]);
            Ws[kq + 0][c] = v.x; Ws[kq + 1][c] = v.y;
            Ws[kq + 2][c] = v.z; Ws[kq + 3][c] = v.w;
        }
        __syncthreads();
#pragma unroll
        for (int k = 0; k < 32; k++) {
            float4 a0 = *reinterpret_cast<const float4*>(&As[k][ty * 8]);
            float4 a1 = *reinterpret_cast<const float4*>(&As[k][ty * 8 + 4]);
            float4 w  = *reinterpret_cast<const float4*>(&Ws[k][tx * 4]);
            float2 ap[4] = { {a0.x, a0.y}, {a0.z, a0.w}, {a1.x, a1.y}, {a1.z, a1.w} };
            float2 wd[4] = { {w.x, w.x}, {w.y, w.y}, {w.z, w.z}, {w.w, w.w} };
#pragma unroll
            for (int rp = 0; rp < 4; rp++)
#pragma unroll
                for (int j = 0; j < 4; j++)
                    acc[rp][j] = ffma2(ap[rp], wd[j], acc[rp][j]);
        }
        __syncthreads();
    }

    float4 bv = make_float4(0.f, 0.f, 0.f, 0.f);
    if (BIAS) bv = *reinterpret_cast<const float4*>(&bias[tx * 4]);
#pragma unroll
    for (int rp = 0; rp < 4; rp++) {
#pragma unroll
        for (int s = 0; s < 2; s++) {
            int r = row0 + ty * 8 + rp * 2 + s;
            if (r < M) {
                float4 o;
                o.x = (s ? acc[rp][0].y : acc[rp][0].x) + bv.x;
                o.y = (s ? acc[rp][1].y : acc[rp][1].x) + bv.y;
                o.z = (s ? acc[rp][2].y : acc[rp][2].x) + bv.z;
                o.w = (s ? acc[rp][3].y : acc[rp][3].x) + bv.w;
                if (ADDAGG) {
                    float sc = __ldg(&inv[r]);
                    float4 av = *reinterpret_cast<const float4*>(&aggY[(size_t)r * CH + tx * 4]);
                    o.x = fmaf(av.x, sc, o.x);
                    o.y = fmaf(av.y, sc, o.y);
                    o.z = fmaf(av.z, sc, o.z);
                    o.w = fmaf(av.w, sc, o.w);
                }
                if (RELU) {
                    o.x = fmaxf(o.x, 0.f); o.y = fmaxf(o.y, 0.f);
                    o.z = fmaxf(o.z, 0.f); o.w = fmaxf(o.w, 0.f);
                }
                *reinterpret_cast<float4*>(&out[(size_t)r * CH + tx * 4]) = o;
            }
        }
    }
}

// ---------------- mentor SAGE layer GEMM (K=128, R4 proven body) ---------------
template <bool RELU>
__global__ __launch_bounds__(256)
void sage_kernel(const float* __restrict__ Agg, const float* __restrict__ inv,
                 const float* __restrict__ Xs,
                 const float* __restrict__ Wl, const float* __restrict__ Wr,
                 const float* __restrict__ bias, float* __restrict__ out, int M) {
    __shared__ float As[32][132];
    __shared__ float Ws[32][68];
    int tid = threadIdx.x;
    int tx = tid & 15, ty = tid >> 4;
    int row0 = blockIdx.x * 128;

    float2 acc[4][4];
#pragma unroll
    for (int i = 0; i < 4; i++)
#pragma unroll
        for (int j = 0; j < 4; j++) acc[i][j] = make_float2(0.f, 0.f);

    for (int tt = 0; tt < 4; tt++) {
        const float* A  = (tt < 2) ? Agg : Xs;
        const float* Wp = (tt < 2) ? Wl  : Wr;
        bool do_scale = (tt < 2);
        int kt = (tt & 1) * 32;
#pragma unroll
        for (int i = 0; i < 4; i++) {
            int idx = tid + 256 * i;
            int r = idx >> 3;
            int kq = (idx & 7) << 2;
            int grow = row0 + r;
            float4 v = make_float4(0.f, 0.f, 0.f, 0.f);
            if (grow < M) {
                v = *reinterpret_cast<const float4*>(&A[(size_t)grow * CH + kt + kq]);
                if (do_scale) {
                    float sc = __ldg(&inv[grow]);
                    v.x *= sc; v.y *= sc; v.z *= sc; v.w *= sc;
                }
            }
            As[kq + 0][r] = v.x; As[kq + 1][r] = v.y;
            As[kq + 2][r] = v.z; As[kq + 3][r] = v.w;
        }
#pragma unroll
        for (int i = 0; i < 2; i++) {
            int idx = tid + 256 * i;
            int c = idx >> 3;
            int kq = (idx & 7) << 2;
            float4 v = *reinterpret_cast<const float4*>(&Wp[(size_t)c * CH + kt + kq]);
            Ws[kq + 0][c] = v.x; Ws[kq + 1][c] = v.y;
            Ws[kq + 2][c] = v.z; Ws[kq + 3][c] = v.w;
        }
        __syncthreads();
#pragma unroll
        for (int k = 0; k < 32; k++) {
            float4 a0 = *reinterpret_cast<const float4*>(&As[k][ty * 8]);
            float4 a1 = *reinterpret_cast<const float4*>(&As[k][ty * 8 + 4]);
            float4 w  = *reinterpret_cast<const float4*>(&Ws[k][tx * 4]);
            float2 ap[4] = { {a0.x, a0.y}, {a0.z, a0.w}, {a1.x, a1.y}, {a1.z, a1.w} };
            float2 wd[4] = { {w.x, w.x}, {w.y, w.y}, {w.z, w.z}, {w.w, w.w} };
#pragma unroll
            for (int rp = 0; rp < 4; rp++)
#pragma unroll
                for (int j = 0; j < 4; j++)
                    acc[rp][j] = ffma2(ap[rp], wd[j], acc[rp][j]);
        }
        __syncthreads();
    }

    float4 bv = *reinterpret_cast<const float4*>(&bias[tx * 4]);
#pragma unroll
    for (int rp = 0; rp < 4; rp++) {
#pragma unroll
        for (int s = 0; s < 2; s++) {
            int r = row0 + ty * 8 + rp * 2 + s;
            if (r < M) {
                float4 o;
                o.x = (s ? acc[rp][0].y : acc[rp][0].x) + bv.x;
                o.y = (s ? acc[rp][1].y : acc[rp][1].x) + bv.y;
                o.z = (s ? acc[rp][2].y : acc[rp][2].x) + bv.z;
                o.w = (s ? acc[rp][3].y : acc[rp][3].x) + bv.w;
                if (RELU) {
                    o.x = fmaxf(o.x, 0.f); o.y = fmaxf(o.y, 0.f);
                    o.z = fmaxf(o.z, 0.f); o.w = fmaxf(o.w, 0.f);
                }
                *reinterpret_cast<float4*>(&out[(size_t)r * CH + tx * 4]) = o;
            }
        }
    }
}

// ---------------- edge dot-product classifier --------------------------------
__global__ void edge_dot_kernel(const float* __restrict__ xt, const float* __restrict__ xm,
                                const int* __restrict__ es, const int* __restrict__ ed,
                                float* __restrict__ out, int E) {
    int t = blockIdx.x * blockDim.x + threadIdx.x;
    int e = t >> 4;
    if (e >= E) return;
    int c4 = (t & 15) << 2;
    int s = __ldg(&es[e]);
    int d = __ldg(&ed[e]);
    float4 a = *reinterpret_cast<const float4*>(&xt[(size_t)s * CH + c4]);
    float4 b = *reinterpret_cast<const float4*>(&xm[(size_t)d * CH + c4]);
    float p = a.x * b.x + a.y * b.y + a.z * b.z + a.w * b.w;
    p += __shfl_down_sync(0xffffffffu, p, 8);
    p += __shfl_down_sync(0xffffffffu, p, 4);
    p += __shfl_down_sync(0xffffffffu, p, 2);
    p += __shfl_down_sync(0xffffffffu, p, 1);
    if ((t & 15) == 0) out[e] = p;
}

// ---------------- launch -----------------------------------------------------
extern "C" void kernel_launch(void* const* d_in, const int* in_sizes, int n_in,
                              void* d_out, int out_size) {
    const float* x_thesis  = (const float*)d_in[0];
    const int*   thesis_id = (const int*)d_in[1];
    const int*   mentor_id = (const int*)d_in[2];
    const int*   edge_src  = (const int*)d_in[3];
    const int*   edge_dst  = (const int*)d_in[4];
    const int*   el_src    = (const int*)d_in[5];
    const int*   el_dst    = (const int*)d_in[6];
    const float* lin_W     = (const float*)d_in[7];
    const float* lin_b     = (const float*)d_in[8];
    const float* emb_t     = (const float*)d_in[9];
    const float* emb_m     = (const float*)d_in[10];
    const float* Wl_tm0    = (const float*)d_in[11];
    const float* Wr_tm0    = (const float*)d_in[12];
    const float* b_tm0     = (const float*)d_in[13];
    const float* Wl_mt0    = (const float*)d_in[14];
    const float* Wr_mt0    = (const float*)d_in[15];
    const float* b_mt0     = (const float*)d_in[16];
    const float* Wl_tm1    = (const float*)d_in[17];
    const float* Wr_tm1    = (const float*)d_in[18];
    const float* b_tm1     = (const float*)d_in[19];
    const float* Wl_mt1    = (const float*)d_in[20];
    const float* Wr_mt1    = (const float*)d_in[21];
    const float* b_mt1     = (const float*)d_in[22];
    float* out = (float*)d_out;

    int nt = in_sizes[1];
    int nm = in_sizes[2];
    int E  = in_sizes[3];
    int EL = in_sizes[5];

    void *p_xt0, *p_xt1, *p_xt2, *p_aggt, *p_xm0, *p_xm1, *p_xm2, *p_aggm, *p_ym;
    void *p_cntt, *p_cntm, *p_invt, *p_invm;
    cudaGetSymbolAddress(&p_xt0, g_xt0);   cudaGetSymbolAddress(&p_xt1, g_xt1);
    cudaGetSymbolAddress(&p_xt2, g_xt2);   cudaGetSymbolAddress(&p_aggt, g_aggt);
    cudaGetSymbolAddress(&p_xm0, g_xm0);   cudaGetSymbolAddress(&p_xm1, g_xm1);
    cudaGetSymbolAddress(&p_xm2, g_xm2);   cudaGetSymbolAddress(&p_aggm, g_aggm);
    cudaGetSymbolAddress(&p_ym, g_ym);
    cudaGetSymbolAddress(&p_cntt, g_cnt_t); cudaGetSymbolAddress(&p_cntm, g_cnt_m);
    cudaGetSymbolAddress(&p_invt, g_inv_t); cudaGetSymbolAddress(&p_invm, g_inv_m);

    float* xt0 = (float*)p_xt0; float* xt1 = (float*)p_xt1; float* xt2 = (float*)p_xt2;
    float* aggt = (float*)p_aggt;
    float* xm0 = (float*)p_xm0; float* xm1 = (float*)p_xm1; float* xm2 = (float*)p_xm2;
    float* aggm = (float*)p_aggm; float* ym = (float*)p_ym;
    int* cntt = (int*)p_cntt; int* cntm = (int*)p_cntm;
    float* invt = (float*)p_invt; float* invm = (float*)p_invm;

    cudaFuncSetAttribute(encoder_wmma_kernel,
                         cudaFuncAttributeMaxDynamicSharedMemorySize, ENC_SMEM);

    const int TB = 256;
    int gridE16  = (E * 16 + TB - 1) / TB;
    int gridEL16 = (EL * 16 + TB - 1) / TB;
    int gridNT   = (nt + 127) / 128;
    int gridNM   = (nm + 127) / 128;

    // ---- exactly 5 launches before the encoder so ncu (-s 5 -c 1) captures it --
    cudaMemsetAsync(cntt, 0, (size_t)nt * sizeof(int));
    cudaMemsetAsync(cntm, 0, (size_t)nm * sizeof(int));
    degree_kernel<<<(E + TB - 1) / TB, TB>>>(edge_src, edge_dst, E);
    recip_kernel<<<(nt + TB - 1) / TB, TB>>>(cntt, invt, nt);
    recip_kernel<<<(nm + TB - 1) / TB, TB>>>(cntm, invm, nm);

    encoder_wmma_kernel<<<gridNT, TB, ENC_SMEM>>>(x_thesis, lin_W, lin_b, emb_t,
                                                  thesis_id, xt0);
    gather_rows_kernel<<<(nm * 16 + TB - 1) / TB, TB>>>(emb_m, mentor_id, xm0, nm);

    // ---- layer 0 ----
    gemm64_kernel<false, false, false><<<gridNM, TB>>>(xm0, Wl_mt0, nullptr, nullptr, nullptr, ym, nm);
    cudaMemsetAsync(aggm, 0, (size_t)nm * CH * sizeof(float));
    cudaMemsetAsync(aggt, 0, (size_t)nt * CH * sizeof(float));
    scatter_kernel<<<gridE16, TB>>>(xt0, edge_src, edge_dst, aggm, E);
    scatter_kernel<<<gridE16, TB>>>(ym, edge_dst, edge_src, aggt, E);
    sage_kernel<true><<<gridNM, TB>>>(aggm, invm, xm0, Wl_tm0, Wr_tm0, b_tm0, xm1, nm);
    gemm64_wmma_kernel<true><<<gridNT, TB>>>(xt0, Wr_mt0, b_mt0, aggt, invt, xt1);

    // ---- layer 1 ----
    gemm64_kernel<false, false, false><<<gridNM, TB>>>(xm1, Wl_mt1, nullptr, nullptr, nullptr, ym, nm);
    cudaMemsetAsync(aggm, 0, (size_t)nm * CH * sizeof(float));
    cudaMemsetAsync(aggt, 0, (size_t)nt * CH * sizeof(float));
    scatter_kernel<<<gridE16, TB>>>(xt1, edge_src, edge_dst, aggm, E);
    scatter_kernel<<<gridE16, TB>>>(ym, edge_dst, edge_src, aggt, E);
    sage_kernel<false><<<gridNM, TB>>>(aggm, invm, xm1, Wl_tm1, Wr_tm1, b_tm1, xm2, nm);
    gemm64_wmma_kernel<false><<<gridNT, TB>>>(xt1, Wr_mt1, b_mt1, aggt, invt, xt2);

    // classifier
    edge_dot_kernel<<<gridEL16, TB>>>(xt2, xm2, el_src, el_dst, out, EL);
}